// round 4
// baseline (speedup 1.0000x reference)
#include <cuda_runtime.h>
#include <cuda_bf16.h>
#include <cuda_fp16.h>
#include <math.h>
#include <stdint.h>

#define NN   100000
#define EE   1600000
#define GG   512
#define IN_C 96
#define HID  128
#define NCLS 100

// ---------------- scratch (device globals; no allocation) ----------------
__device__ float  d_ew[EE];
__device__ int    d_pos[EE];
__device__ int    d_cnt[NN];
__device__ int    d_rowptr[NN + 1];
__device__ float2 d_adj[EE];            // packed (src as int bits, norm)
__device__ float  d_deg[NN];
__device__ float  d_dis[NN];
__device__ __half d_hwh[(size_t)NN * HID];   // GEMM output, fp16 (gather source)
__device__ float  d_curA[(size_t)NN * HID];
__device__ float  d_curB[(size_t)NN * HID];
__device__ float  d_res0[(size_t)NN * HID];
__device__ float  d_xm  [(size_t)NN * HID];
__device__ int    d_gstart[GG + 1];
__device__ float  d_gmean[GG * HID];
__device__ float  d_gmaxv[GG * HID];
// pre-split weights, n-major [128 n][128 k] bf16, hi and lo parts, 5 matrices
__device__ __nv_bfloat16 d_Bh[5 * 128 * 128];
__device__ __nv_bfloat16 d_Bl[5 * 128 * 128];

// ---------------- init ----------------
__global__ void init_k() {
    int i = blockIdx.x * blockDim.x + threadIdx.x;
    if (i < NN) { d_deg[i] = 1.0f; d_cnt[i] = 0; }
    if (i <= GG) d_gstart[i] = NN;
}

// ---------------- edge encoder + degree/count (merged) ----------------
__global__ __launch_bounds__(256) void edge_mlp_k(
    const float* __restrict__ ea, const float* __restrict__ W1,
    const float* __restrict__ b1, const float* __restrict__ W2,
    const float* __restrict__ b2, const int* __restrict__ col)
{
    __shared__ float W1s[8 * 128];
    __shared__ float b1s[128];
    __shared__ float W2s[128];
    int tid = threadIdx.x;
    for (int i = tid; i < 8 * 128; i += 256) W1s[i] = W1[i];
    if (tid < 128) { b1s[tid] = b1[tid]; W2s[tid] = W2[tid]; }
    __syncthreads();
    int e = blockIdx.x * 256 + tid;
    if (e >= EE) return;
    float4 a0 = *(const float4*)(ea + (size_t)e * 8);
    float4 a1 = *(const float4*)(ea + (size_t)e * 8 + 4);
    float a[8] = {a0.x, a0.y, a0.z, a0.w, a1.x, a1.y, a1.z, a1.w};
    const float4* W1v = (const float4*)W1s;
    const float4* b1v = (const float4*)b1s;
    const float4* W2v = (const float4*)W2s;
    float acc = 0.f;
    #pragma unroll 8
    for (int j4 = 0; j4 < 32; j4++) {
        float4 h = b1v[j4];
        #pragma unroll
        for (int k = 0; k < 8; k++) {
            float4 w = W1v[k * 32 + j4];
            h.x = fmaf(a[k], w.x, h.x);
            h.y = fmaf(a[k], w.y, h.y);
            h.z = fmaf(a[k], w.z, h.z);
            h.w = fmaf(a[k], w.w, h.w);
        }
        h.x = fmaxf(h.x, 0.f); h.y = fmaxf(h.y, 0.f);
        h.z = fmaxf(h.z, 0.f); h.w = fmaxf(h.w, 0.f);
        float4 w2 = W2v[j4];
        acc = fmaf(h.x, w2.x, acc);
        acc = fmaf(h.y, w2.y, acc);
        acc = fmaf(h.z, w2.z, acc);
        acc = fmaf(h.w, w2.w, acc);
    }
    float x = acc + b2[0];
    float sp = (x > 15.f) ? x : log1pf(expf(x));
    float ew = sp + 1e-4f;
    d_ew[e] = ew;
    int c = col[e];
    d_pos[e] = atomicAdd(&d_cnt[c], 1);
    atomicAdd(&d_deg[c], ew);
}

__global__ void dis_k() {
    int i = blockIdx.x * blockDim.x + threadIdx.x;
    if (i < NN) d_dis[i] = rsqrtf(d_deg[i]);
}

// ---------------- single-block exclusive scan -> rowptr ----------------
__global__ __launch_bounds__(1024) void scan_k() {
    __shared__ int wsum[32];
    int tid = threadIdx.x, lane = tid & 31, wid = tid >> 5;
    int carry = 0;
    if (tid == 0) d_rowptr[0] = 0;
    for (int base = 0; base < NN; base += 1024) {
        int i = base + tid;
        int v = (i < NN) ? d_cnt[i] : 0;
        int s = v;
        #pragma unroll
        for (int o = 1; o < 32; o <<= 1) {
            int t = __shfl_up_sync(0xffffffffu, s, o);
            if (lane >= o) s += t;
        }
        if (lane == 31) wsum[wid] = s;
        __syncthreads();
        if (wid == 0) {
            int ws = wsum[lane];
            #pragma unroll
            for (int o = 1; o < 32; o <<= 1) {
                int t = __shfl_up_sync(0xffffffffu, ws, o);
                if (lane >= o) ws += t;
            }
            wsum[lane] = ws;
        }
        __syncthreads();
        int wexcl = (wid > 0) ? wsum[wid - 1] : 0;
        if (i < NN) d_rowptr[i + 1] = carry + wexcl + s;
        carry += wsum[31];
        __syncthreads();
    }
}

// ---------------- fill CSR (packed src+norm) ----------------
__global__ void fill_k(const int* __restrict__ row, const int* __restrict__ col) {
    int e = blockIdx.x * blockDim.x + threadIdx.x;
    if (e >= EE) return;
    int r = row[e], c = col[e];
    int j = d_rowptr[c] + d_pos[e];
    float2 v;
    v.x = __int_as_float(r);
    v.y = d_dis[r] * d_ew[e] * d_dis[c];
    d_adj[j] = v;
}

// ---------------- weight prep: split fp32 -> bf16 hi/lo, n-major [n][k] ----------------
__global__ __launch_bounds__(128) void prep_k(
    const float* __restrict__ resW, const float* __restrict__ W0,
    const float* __restrict__ W1, const float* __restrict__ W2,
    const float* __restrict__ W3)
{
    int m = blockIdx.x, n = threadIdx.x;
    const float* W; int K;
    switch (m) {
        case 0: W = resW; K = 96; break;
        case 1: W = W0;   K = 96; break;
        case 2: W = W1;   K = 128; break;
        case 3: W = W2;   K = 128; break;
        default: W = W3;  K = 128; break;
    }
    __nv_bfloat16* bh = d_Bh + (size_t)m * 16384 + (size_t)n * 128;
    __nv_bfloat16* bl = d_Bl + (size_t)m * 16384 + (size_t)n * 128;
    for (int k = 0; k < 128; k++) {
        float v = (k < K) ? W[(size_t)k * HID + n] : 0.f;
        __nv_bfloat16 h = __float2bfloat16_rn(v);
        bh[k] = h;
        bl[k] = __float2bfloat16_rn(v - __bfloat162float(h));
    }
}

// ---------------- HMMA bf16 split GEMM: C[M,128] = A[M,K] @ W + (bias) ----------------
#define PITCH 136
#define BUFSZ (128 * PITCH)
#define SMEM_GEMM (4 * BUFSZ * 2)

__device__ __forceinline__ void mma16816(float* c, const uint32_t* a, const uint32_t* b) {
    asm volatile(
        "mma.sync.aligned.m16n8k16.row.col.f32.bf16.bf16.f32 "
        "{%0,%1,%2,%3}, {%4,%5,%6,%7}, {%8,%9}, {%0,%1,%2,%3};"
        : "+f"(c[0]), "+f"(c[1]), "+f"(c[2]), "+f"(c[3])
        : "r"(a[0]), "r"(a[1]), "r"(a[2]), "r"(a[3]), "r"(b[0]), "r"(b[1]));
}

// asel: 0 -> Ain, 1 -> d_curA, 2 -> d_curB ; osel: 0 -> d_hwh (half), 1 -> d_res0 (f32)
__global__ __launch_bounds__(256) void mma_gemm_k(
    const float* __restrict__ Ain, int asel, int osel, int mat,
    int lda, const float* __restrict__ bias)
{
    extern __shared__ __nv_bfloat16 sm[];
    __nv_bfloat16* AhiS = sm;
    __nv_bfloat16* AloS = sm + BUFSZ;
    __nv_bfloat16* BhS  = sm + 2 * BUFSZ;
    __nv_bfloat16* BlS  = sm + 3 * BUFSZ;
    __shared__ float biasS[128];

    const float* A = (asel == 1) ? d_curA : (asel == 2) ? d_curB : Ain;
    int tid = threadIdx.x;
    int r0 = blockIdx.x * 128;

    if (tid < 128) biasS[tid] = bias ? bias[tid] : 0.f;

    // stage A (fp32 -> hi/lo bf16)
    {
        int rr = tid >> 5;           // 0..7
        int cc = (tid & 31) * 4;     // 0..124
        #pragma unroll 4
        for (int it = 0; it < 16; it++) {
            int r = it * 8 + rr;
            int R = r0 + r;
            float4 v = make_float4(0.f, 0.f, 0.f, 0.f);
            if (R < NN && cc < lda)
                v = *(const float4*)(A + (size_t)R * lda + cc);
            __nv_bfloat16 h0 = __float2bfloat16_rn(v.x);
            __nv_bfloat16 h1 = __float2bfloat16_rn(v.y);
            __nv_bfloat16 h2 = __float2bfloat16_rn(v.z);
            __nv_bfloat16 h3 = __float2bfloat16_rn(v.w);
            __nv_bfloat16 l0 = __float2bfloat16_rn(v.x - __bfloat162float(h0));
            __nv_bfloat16 l1 = __float2bfloat16_rn(v.y - __bfloat162float(h1));
            __nv_bfloat16 l2 = __float2bfloat16_rn(v.z - __bfloat162float(h2));
            __nv_bfloat16 l3 = __float2bfloat16_rn(v.w - __bfloat162float(h3));
            uint2 ph, pl;
            ph.x = ((uint32_t)__bfloat16_as_ushort(h1) << 16) | __bfloat16_as_ushort(h0);
            ph.y = ((uint32_t)__bfloat16_as_ushort(h3) << 16) | __bfloat16_as_ushort(h2);
            pl.x = ((uint32_t)__bfloat16_as_ushort(l1) << 16) | __bfloat16_as_ushort(l0);
            pl.y = ((uint32_t)__bfloat16_as_ushort(l3) << 16) | __bfloat16_as_ushort(l2);
            *(uint2*)(AhiS + r * PITCH + cc) = ph;
            *(uint2*)(AloS + r * PITCH + cc) = pl;
        }
    }
    // stage B (already split, n-major)
    {
        int rr = tid >> 5;
        int cc = (tid & 31) * 4;
        const __nv_bfloat16* gh = d_Bh + (size_t)mat * 16384;
        const __nv_bfloat16* gl = d_Bl + (size_t)mat * 16384;
        #pragma unroll 4
        for (int it = 0; it < 16; it++) {
            int n = it * 8 + rr;
            *(uint2*)(BhS + n * PITCH + cc) = *(const uint2*)(gh + n * 128 + cc);
            *(uint2*)(BlS + n * PITCH + cc) = *(const uint2*)(gl + n * 128 + cc);
        }
    }
    __syncthreads();

    int wid = tid >> 5, lane = tid & 31;
    int g = lane >> 2, tig = lane & 3;
    int wr = (wid & 3) * 32;          // warp M base
    int wc = (wid >> 2) * 64;         // warp N base

    float cacc[2][8][4];
    #pragma unroll
    for (int mt = 0; mt < 2; mt++)
        #pragma unroll
        for (int nt = 0; nt < 8; nt++)
            #pragma unroll
            for (int q = 0; q < 4; q++) cacc[mt][nt][q] = 0.f;

    #pragma unroll
    for (int p = 0; p < 3; p++) {
        const __nv_bfloat16* As = (p == 1) ? AloS : AhiS;
        const __nv_bfloat16* Bs = (p == 2) ? BlS : BhS;
        #pragma unroll
        for (int ks = 0; ks < 8; ks++) {
            int k0 = ks * 16;
            uint32_t af[2][4];
            #pragma unroll
            for (int mt = 0; mt < 2; mt++) {
                const __nv_bfloat16* base = As + (wr + mt * 16) * PITCH + k0;
                af[mt][0] = *(const uint32_t*)(base + g * PITCH + 2 * tig);
                af[mt][1] = *(const uint32_t*)(base + (g + 8) * PITCH + 2 * tig);
                af[mt][2] = *(const uint32_t*)(base + g * PITCH + 8 + 2 * tig);
                af[mt][3] = *(const uint32_t*)(base + (g + 8) * PITCH + 8 + 2 * tig);
            }
            #pragma unroll
            for (int nt = 0; nt < 8; nt++) {
                uint32_t bf[2];
                const __nv_bfloat16* nb = Bs + (wc + nt * 8 + g) * PITCH + k0;
                bf[0] = *(const uint32_t*)(nb + 2 * tig);
                bf[1] = *(const uint32_t*)(nb + 8 + 2 * tig);
                mma16816(cacc[0][nt], af[0], bf);
                mma16816(cacc[1][nt], af[1], bf);
            }
        }
    }

    // epilogue
    #pragma unroll
    for (int mt = 0; mt < 2; mt++) {
        int row = r0 + wr + mt * 16 + g;
        #pragma unroll
        for (int nt = 0; nt < 8; nt++) {
            int col = wc + nt * 8 + 2 * tig;
            float b0 = biasS[col], b1 = biasS[col + 1];
            float v00 = cacc[mt][nt][0] + b0, v01 = cacc[mt][nt][1] + b1;
            float v10 = cacc[mt][nt][2] + b0, v11 = cacc[mt][nt][3] + b1;
            if (osel == 1) {
                if (row < NN)
                    *(float2*)(d_res0 + (size_t)row * HID + col) = make_float2(v00, v01);
                if (row + 8 < NN)
                    *(float2*)(d_res0 + (size_t)(row + 8) * HID + col) = make_float2(v10, v11);
            } else {
                if (row < NN)
                    *(__half2*)(d_hwh + (size_t)row * HID + col) =
                        __floats2half2_rn(v00, v01);
                if (row + 8 < NN)
                    *(__half2*)(d_hwh + (size_t)(row + 8) * HID + col) =
                        __floats2half2_rn(v10, v11);
            }
        }
    }
}

// ---------------- fused aggregate + bias + LN + residual + relu + mean-acc ----------------
__global__ __launch_bounds__(256) void agg_ln_k(
    const float* __restrict__ cb, const float* __restrict__ gam,
    const float* __restrict__ bet, int rsel, int osel, int first)
{
    int n = (blockIdx.x * 256 + threadIdx.x) >> 5;
    if (n >= NN) return;
    int lane = threadIdx.x & 31;
    const float* resid = (rsel == 0) ? d_res0 : (rsel == 1) ? d_curA : d_curB;
    float* outp = (osel == 1) ? d_curA : d_curB;

    float dn = d_dis[n];
    float sn = dn * dn;
    float4 acc = ((const float4*)cb)[lane];
    {
        uint2 raw = *(const uint2*)(d_hwh + (size_t)n * HID + lane * 4);
        float2 f0 = __half22float2(*(__half2*)&raw.x);
        float2 f1 = __half22float2(*(__half2*)&raw.y);
        acc.x = fmaf(sn, f0.x, acc.x);
        acc.y = fmaf(sn, f0.y, acc.y);
        acc.z = fmaf(sn, f1.x, acc.z);
        acc.w = fmaf(sn, f1.y, acc.w);
    }

    int jb = d_rowptr[n], je = d_rowptr[n + 1];
    for (int j = jb; j < je; j++) {
        float2 a = d_adj[j];
        int s = __float_as_int(a.x);
        float w = a.y;
        uint2 raw = *(const uint2*)(d_hwh + (size_t)s * HID + lane * 4);
        float2 f0 = __half22float2(*(__half2*)&raw.x);
        float2 f1 = __half22float2(*(__half2*)&raw.y);
        acc.x = fmaf(w, f0.x, acc.x);
        acc.y = fmaf(w, f0.y, acc.y);
        acc.z = fmaf(w, f1.x, acc.z);
        acc.w = fmaf(w, f1.y, acc.w);
    }

    float ss = acc.x + acc.y + acc.z + acc.w;
    #pragma unroll
    for (int o = 16; o > 0; o >>= 1) ss += __shfl_xor_sync(0xffffffffu, ss, o);
    float mu = ss * (1.f / 128.f);
    float dx0 = acc.x - mu, dx1 = acc.y - mu, dx2 = acc.z - mu, dx3 = acc.w - mu;
    float q = dx0 * dx0 + dx1 * dx1 + dx2 * dx2 + dx3 * dx3;
    #pragma unroll
    for (int o = 16; o > 0; o >>= 1) q += __shfl_xor_sync(0xffffffffu, q, o);
    float rstd = rsqrtf(q * (1.f / 128.f) + 1e-5f);

    float4 gv = ((const float4*)gam)[lane];
    float4 bv = ((const float4*)bet)[lane];
    float4 rv = ((const float4*)resid)[(size_t)n * 32 + lane];
    float4 h;
    h.x = fmaxf(fmaf(gv.x, dx0 * rstd, bv.x) + rv.x, 0.f);
    h.y = fmaxf(fmaf(gv.y, dx1 * rstd, bv.y) + rv.y, 0.f);
    h.z = fmaxf(fmaf(gv.z, dx2 * rstd, bv.z) + rv.z, 0.f);
    h.w = fmaxf(fmaf(gv.w, dx3 * rstd, bv.w) + rv.w, 0.f);

    ((float4*)outp)[(size_t)n * 32 + lane] = h;
    float4* xm4 = (float4*)d_xm;
    if (first) {
        xm4[(size_t)n * 32 + lane] = h;
    } else {
        float4 t = xm4[(size_t)n * 32 + lane];
        t.x += h.x; t.y += h.y; t.z += h.z; t.w += h.w;
        xm4[(size_t)n * 32 + lane] = t;
    }
}

// ---------------- graph segment boundaries ----------------
__global__ void mark_k(const int* __restrict__ batch) {
    int n = blockIdx.x * blockDim.x + threadIdx.x;
    if (n >= NN) return;
    int b = batch[n];
    if (n == 0 || batch[n - 1] != b) atomicMin(&d_gstart[b], n);
}

__global__ __launch_bounds__(512) void fix_k() {
    __shared__ int s[520];
    int t = threadIdx.x;
    s[t] = d_gstart[t];
    if (t == 0) s[GG] = NN;
    __syncthreads();
    for (int o = 1; o <= GG; o <<= 1) {
        int v = s[t];
        int u = (t + o <= GG) ? s[t + o] : NN;
        __syncthreads();
        s[t] = min(v, u);
        __syncthreads();
    }
    d_gstart[t] = s[t];
}

// ---------------- pooling ----------------
__global__ __launch_bounds__(128) void pool_k() {
    int g = blockIdx.x, c = threadIdx.x;
    int s = d_gstart[g], e = d_gstart[g + 1];
    float sum = 0.f, mx = 0.f;
    for (int n = s; n < e; n++) {
        float v = d_xm[(size_t)n * HID + c] * 0.25f;
        sum += v;
        mx = fmaxf(mx, v);
    }
    int cnt = e - s;
    d_gmean[g * HID + c] = sum / (float)max(cnt, 1);
    d_gmaxv[g * HID + c] = mx;
}

// ---------------- head ----------------
__global__ __launch_bounds__(128) void head_k(
    const float* __restrict__ hW1, const float* __restrict__ hb1,
    const float* __restrict__ hW2, const float* __restrict__ hb2,
    float* __restrict__ out)
{
    __shared__ float gf[256];
    __shared__ float h1s[128];
    int g = blockIdx.x, t = threadIdx.x;
    gf[t] = d_gmean[g * HID + t];
    gf[128 + t] = d_gmaxv[g * HID + t];
    __syncthreads();
    float acc = hb1[t];
    #pragma unroll 8
    for (int k = 0; k < 256; k++) acc = fmaf(gf[k], hW1[k * HID + t], acc);
    h1s[t] = fmaxf(acc, 0.f);
    __syncthreads();
    if (t < NCLS) {
        float o = hb2[t];
        #pragma unroll 8
        for (int k = 0; k < 128; k++) o = fmaf(h1s[k], hW2[k * NCLS + t], o);
        out[g * NCLS + t] = o;
    }
}

// ---------------- launcher ----------------
extern "C" void kernel_launch(void* const* d_in, const int* in_sizes, int n_in,
                              void* d_out, int out_size) {
    const float* x     = (const float*)d_in[0];
    const int*   ei    = (const int*)d_in[1];
    const int*   batch = (const int*)d_in[2];
    const float* ea    = (const float*)d_in[3];
    const float* eeW1  = (const float*)d_in[4];
    const float* eeb1  = (const float*)d_in[5];
    const float* eeW2  = (const float*)d_in[6];
    const float* eeb2  = (const float*)d_in[7];
    const float* W[4]  = {(const float*)d_in[8],  (const float*)d_in[10],
                          (const float*)d_in[12], (const float*)d_in[14]};
    const float* cbp[4]= {(const float*)d_in[9],  (const float*)d_in[11],
                          (const float*)d_in[13], (const float*)d_in[15]};
    const float* gm[4] = {(const float*)d_in[16], (const float*)d_in[18],
                          (const float*)d_in[20], (const float*)d_in[22]};
    const float* be[4] = {(const float*)d_in[17], (const float*)d_in[19],
                          (const float*)d_in[21], (const float*)d_in[23]};
    const float* resW  = (const float*)d_in[24];
    const float* resB  = (const float*)d_in[25];
    const float* hW1   = (const float*)d_in[26];
    const float* hb1   = (const float*)d_in[27];
    const float* hW2   = (const float*)d_in[28];
    const float* hb2   = (const float*)d_in[29];
    float* out = (float*)d_out;

    cudaFuncSetAttribute(mma_gemm_k, cudaFuncAttributeMaxDynamicSharedMemorySize, SMEM_GEMM);

    const int nblkN = (NN + 255) / 256;
    const int nblkE = (EE + 255) / 256;
    const int tileG = (NN + 127) / 128;
    const int aggG  = (NN + 7) / 8;

    init_k<<<nblkN, 256>>>();
    edge_mlp_k<<<nblkE, 256>>>(ea, eeW1, eeb1, eeW2, eeb2, ei + EE);
    dis_k<<<nblkN, 256>>>();
    scan_k<<<1, 1024>>>();
    fill_k<<<nblkE, 256>>>(ei, ei + EE);
    prep_k<<<5, 128>>>(resW, W[0], W[1], W[2], W[3]);

    // residual projection for layer 0: x @ resW + resB -> d_res0
    mma_gemm_k<<<tileG, 256, SMEM_GEMM>>>(x, 0, 1, 0, IN_C, resB);
    // layer 0
    mma_gemm_k<<<tileG, 256, SMEM_GEMM>>>(x, 0, 0, 1, IN_C, nullptr);
    agg_ln_k<<<aggG, 256>>>(cbp[0], gm[0], be[0], 0, 1, 1);
    // layer 1
    mma_gemm_k<<<tileG, 256, SMEM_GEMM>>>(nullptr, 1, 0, 2, HID, nullptr);
    agg_ln_k<<<aggG, 256>>>(cbp[1], gm[1], be[1], 1, 2, 0);
    // layer 2
    mma_gemm_k<<<tileG, 256, SMEM_GEMM>>>(nullptr, 2, 0, 3, HID, nullptr);
    agg_ln_k<<<aggG, 256>>>(cbp[2], gm[2], be[2], 2, 1, 0);
    // layer 3
    mma_gemm_k<<<tileG, 256, SMEM_GEMM>>>(nullptr, 1, 0, 4, HID, nullptr);
    agg_ln_k<<<aggG, 256>>>(cbp[3], gm[3], be[3], 1, 2, 0);

    mark_k<<<nblkN, 256>>>(batch);
    fix_k<<<1, 512>>>();
    pool_k<<<GG, 128>>>();
    head_k<<<GG, 128>>>(hW1, hb1, hW2, hb2, out);
}

// round 5
// speedup vs baseline: 1.1385x; 1.1385x over previous
#include <cuda_runtime.h>
#include <cuda_bf16.h>
#include <cuda_fp16.h>
#include <math.h>
#include <stdint.h>

#define NN   100000
#define EE   1600000
#define GG   512
#define IN_C 96
#define HID  128
#define NCLS 100
#define SCAN_BLOCKS 98   // ceil(100000/1024)

// ---------------- scratch (device globals; no allocation) ----------------
__device__ float  d_ew[EE];
__device__ int    d_pos[EE];
__device__ int    d_cnt[NN];
__device__ int    d_rowptr[NN + 1];
__device__ int    d_bsum[SCAN_BLOCKS];
__device__ int    d_boff[SCAN_BLOCKS];
__device__ float2 d_adj[EE];            // packed (src as int bits, norm)
__device__ float  d_deg[NN];
__device__ float  d_dis[NN];
__device__ __half d_hwh[(size_t)NN * HID];   // GEMM output, fp16 (gather source)
__device__ float  d_curA[(size_t)NN * HID];
__device__ float  d_curB[(size_t)NN * HID];
__device__ float  d_res0[(size_t)NN * HID];
__device__ float  d_xm  [(size_t)NN * HID];
__device__ int    d_gstart[GG + 1];
__device__ float  d_gmean[GG * HID];
__device__ float  d_gmaxv[GG * HID];
// pre-split weights, n-major [128 n][128 k] bf16, hi and lo parts, 5 matrices
__device__ __nv_bfloat16 d_Bh[5 * 128 * 128];
__device__ __nv_bfloat16 d_Bl[5 * 128 * 128];

// ---------------- init ----------------
__global__ void init_k() {
    int i = blockIdx.x * blockDim.x + threadIdx.x;
    if (i < NN) { d_deg[i] = 1.0f; d_cnt[i] = 0; }
    if (i <= GG) d_gstart[i] = NN;
}

// ---------------- edge encoder + degree/count (merged) ----------------
__global__ __launch_bounds__(256) void edge_mlp_k(
    const float* __restrict__ ea, const float* __restrict__ W1,
    const float* __restrict__ b1, const float* __restrict__ W2,
    const float* __restrict__ b2, const int* __restrict__ col)
{
    __shared__ float W1s[8 * 128];
    __shared__ float b1s[128];
    __shared__ float W2s[128];
    int tid = threadIdx.x;
    for (int i = tid; i < 8 * 128; i += 256) W1s[i] = W1[i];
    if (tid < 128) { b1s[tid] = b1[tid]; W2s[tid] = W2[tid]; }
    __syncthreads();
    int e = blockIdx.x * 256 + tid;
    if (e >= EE) return;
    float4 a0 = *(const float4*)(ea + (size_t)e * 8);
    float4 a1 = *(const float4*)(ea + (size_t)e * 8 + 4);
    float a[8] = {a0.x, a0.y, a0.z, a0.w, a1.x, a1.y, a1.z, a1.w};
    const float4* W1v = (const float4*)W1s;
    const float4* b1v = (const float4*)b1s;
    const float4* W2v = (const float4*)W2s;
    float acc = 0.f;
    #pragma unroll 8
    for (int j4 = 0; j4 < 32; j4++) {
        float4 h = b1v[j4];
        #pragma unroll
        for (int k = 0; k < 8; k++) {
            float4 w = W1v[k * 32 + j4];
            h.x = fmaf(a[k], w.x, h.x);
            h.y = fmaf(a[k], w.y, h.y);
            h.z = fmaf(a[k], w.z, h.z);
            h.w = fmaf(a[k], w.w, h.w);
        }
        h.x = fmaxf(h.x, 0.f); h.y = fmaxf(h.y, 0.f);
        h.z = fmaxf(h.z, 0.f); h.w = fmaxf(h.w, 0.f);
        float4 w2 = W2v[j4];
        acc = fmaf(h.x, w2.x, acc);
        acc = fmaf(h.y, w2.y, acc);
        acc = fmaf(h.z, w2.z, acc);
        acc = fmaf(h.w, w2.w, acc);
    }
    float x = acc + b2[0];
    float sp = (x > 15.f) ? x : log1pf(expf(x));
    float ew = sp + 1e-4f;
    d_ew[e] = ew;
    int c = col[e];
    d_pos[e] = atomicAdd(&d_cnt[c], 1);
    atomicAdd(&d_deg[c], ew);
}

__global__ void dis_k() {
    int i = blockIdx.x * blockDim.x + threadIdx.x;
    if (i < NN) d_dis[i] = rsqrtf(d_deg[i]);
}

// ---------------- hierarchical scan ----------------
// pass 1: per-block inclusive scan of 1024 counts -> rowptr[i+1] (local), block sums
__global__ __launch_bounds__(1024) void scan1_k() {
    __shared__ int wsum[32];
    int tid = threadIdx.x, lane = tid & 31, wid = tid >> 5;
    int i = blockIdx.x * 1024 + tid;
    int v = (i < NN) ? d_cnt[i] : 0;
    int s = v;
    #pragma unroll
    for (int o = 1; o < 32; o <<= 1) {
        int t = __shfl_up_sync(0xffffffffu, s, o);
        if (lane >= o) s += t;
    }
    if (lane == 31) wsum[wid] = s;
    __syncthreads();
    if (wid == 0) {
        int ws = wsum[lane];
        #pragma unroll
        for (int o = 1; o < 32; o <<= 1) {
            int t = __shfl_up_sync(0xffffffffu, ws, o);
            if (lane >= o) ws += t;
        }
        wsum[lane] = ws;
    }
    __syncthreads();
    int incl = s + ((wid > 0) ? wsum[wid - 1] : 0);
    if (i < NN) d_rowptr[i + 1] = incl;
    if (tid == 1023) d_bsum[blockIdx.x] = incl;
}

// pass 2: single block exclusive-scans the 98 block sums
__global__ __launch_bounds__(128) void scan2_k() {
    int tid = threadIdx.x, lane = tid & 31, wid = tid >> 5;
    __shared__ int wsum[4];
    int v = (tid < SCAN_BLOCKS) ? d_bsum[tid] : 0;
    int s = v;
    #pragma unroll
    for (int o = 1; o < 32; o <<= 1) {
        int t = __shfl_up_sync(0xffffffffu, s, o);
        if (lane >= o) s += t;
    }
    if (lane == 31) wsum[wid] = s;
    __syncthreads();
    int add = 0;
    for (int w = 0; w < 4; w++) if (w < wid) add += wsum[w];
    if (tid < SCAN_BLOCKS) d_boff[tid] = s + add - v;  // exclusive
}

// pass 3: add block offsets
__global__ __launch_bounds__(1024) void scan3_k() {
    int i = blockIdx.x * 1024 + threadIdx.x;
    if (i < NN) d_rowptr[i + 1] += d_boff[blockIdx.x];
    if (i == 0) d_rowptr[0] = 0;
}

// ---------------- fill CSR (packed src+norm) ----------------
__global__ void fill_k(const int* __restrict__ row, const int* __restrict__ col) {
    int e = blockIdx.x * blockDim.x + threadIdx.x;
    if (e >= EE) return;
    int r = row[e], c = col[e];
    int j = d_rowptr[c] + d_pos[e];
    float2 v;
    v.x = __int_as_float(r);
    v.y = d_dis[r] * d_ew[e] * d_dis[c];
    d_adj[j] = v;
}

// ---------------- weight prep: split fp32 -> bf16 hi/lo, n-major [n][k] ----------------
__global__ __launch_bounds__(128) void prep_k(
    const float* __restrict__ resW, const float* __restrict__ W0,
    const float* __restrict__ W1, const float* __restrict__ W2,
    const float* __restrict__ W3)
{
    int m = blockIdx.x, n = threadIdx.x;
    const float* W; int K;
    switch (m) {
        case 0: W = resW; K = 96; break;
        case 1: W = W0;   K = 96; break;
        case 2: W = W1;   K = 128; break;
        case 3: W = W2;   K = 128; break;
        default: W = W3;  K = 128; break;
    }
    __nv_bfloat16* bh = d_Bh + (size_t)m * 16384 + (size_t)n * 128;
    __nv_bfloat16* bl = d_Bl + (size_t)m * 16384 + (size_t)n * 128;
    for (int k = 0; k < 128; k++) {
        float v = (k < K) ? W[(size_t)k * HID + n] : 0.f;
        __nv_bfloat16 h = __float2bfloat16_rn(v);
        bh[k] = h;
        bl[k] = __float2bfloat16_rn(v - __bfloat162float(h));
    }
}

// ---------------- HMMA bf16 split GEMM: C[M,128] = A[M,K] @ W + (bias) ----------------
#define PITCH 136
#define BUFSZ (128 * PITCH)
#define SMEM_GEMM (4 * BUFSZ * 2)

__device__ __forceinline__ void mma16816(float* c, const uint32_t* a, const uint32_t* b) {
    asm volatile(
        "mma.sync.aligned.m16n8k16.row.col.f32.bf16.bf16.f32 "
        "{%0,%1,%2,%3}, {%4,%5,%6,%7}, {%8,%9}, {%0,%1,%2,%3};"
        : "+f"(c[0]), "+f"(c[1]), "+f"(c[2]), "+f"(c[3])
        : "r"(a[0]), "r"(a[1]), "r"(a[2]), "r"(a[3]), "r"(b[0]), "r"(b[1]));
}

// asel: 0 -> Ain, 1 -> d_curA, 2 -> d_curB ; osel: 0 -> d_hwh (half), 1 -> d_res0 (f32)
__global__ __launch_bounds__(256) void mma_gemm_k(
    const float* __restrict__ Ain, int asel, int osel, int mat,
    int lda, const float* __restrict__ bias)
{
    extern __shared__ __nv_bfloat16 sm[];
    __nv_bfloat16* AhiS = sm;
    __nv_bfloat16* AloS = sm + BUFSZ;
    __nv_bfloat16* BhS  = sm + 2 * BUFSZ;
    __nv_bfloat16* BlS  = sm + 3 * BUFSZ;
    __shared__ float biasS[128];

    const float* A = (asel == 1) ? d_curA : (asel == 2) ? d_curB : Ain;
    int tid = threadIdx.x;
    int r0 = blockIdx.x * 128;

    if (tid < 128) biasS[tid] = bias ? bias[tid] : 0.f;

    // stage A (fp32 -> hi/lo bf16)
    {
        int rr = tid >> 5;           // 0..7
        int cc = (tid & 31) * 4;     // 0..124
        #pragma unroll 4
        for (int it = 0; it < 16; it++) {
            int r = it * 8 + rr;
            int R = r0 + r;
            float4 v = make_float4(0.f, 0.f, 0.f, 0.f);
            if (R < NN && cc < lda)
                v = *(const float4*)(A + (size_t)R * lda + cc);
            __nv_bfloat16 h0 = __float2bfloat16_rn(v.x);
            __nv_bfloat16 h1 = __float2bfloat16_rn(v.y);
            __nv_bfloat16 h2 = __float2bfloat16_rn(v.z);
            __nv_bfloat16 h3 = __float2bfloat16_rn(v.w);
            __nv_bfloat16 l0 = __float2bfloat16_rn(v.x - __bfloat162float(h0));
            __nv_bfloat16 l1 = __float2bfloat16_rn(v.y - __bfloat162float(h1));
            __nv_bfloat16 l2 = __float2bfloat16_rn(v.z - __bfloat162float(h2));
            __nv_bfloat16 l3 = __float2bfloat16_rn(v.w - __bfloat162float(h3));
            uint2 ph, pl;
            ph.x = ((uint32_t)__bfloat16_as_ushort(h1) << 16) | __bfloat16_as_ushort(h0);
            ph.y = ((uint32_t)__bfloat16_as_ushort(h3) << 16) | __bfloat16_as_ushort(h2);
            pl.x = ((uint32_t)__bfloat16_as_ushort(l1) << 16) | __bfloat16_as_ushort(l0);
            pl.y = ((uint32_t)__bfloat16_as_ushort(l3) << 16) | __bfloat16_as_ushort(l2);
            *(uint2*)(AhiS + r * PITCH + cc) = ph;
            *(uint2*)(AloS + r * PITCH + cc) = pl;
        }
    }
    // stage B (already split, n-major)
    {
        int rr = tid >> 5;
        int cc = (tid & 31) * 4;
        const __nv_bfloat16* gh = d_Bh + (size_t)mat * 16384;
        const __nv_bfloat16* gl = d_Bl + (size_t)mat * 16384;
        #pragma unroll 4
        for (int it = 0; it < 16; it++) {
            int n = it * 8 + rr;
            *(uint2*)(BhS + n * PITCH + cc) = *(const uint2*)(gh + n * 128 + cc);
            *(uint2*)(BlS + n * PITCH + cc) = *(const uint2*)(gl + n * 128 + cc);
        }
    }
    __syncthreads();

    int wid = tid >> 5, lane = tid & 31;
    int g = lane >> 2, tig = lane & 3;
    int wr = (wid & 3) * 32;          // warp M base
    int wc = (wid >> 2) * 64;         // warp N base

    float cacc[2][8][4];
    #pragma unroll
    for (int mt = 0; mt < 2; mt++)
        #pragma unroll
        for (int nt = 0; nt < 8; nt++)
            #pragma unroll
            for (int q = 0; q < 4; q++) cacc[mt][nt][q] = 0.f;

    #pragma unroll
    for (int p = 0; p < 3; p++) {
        const __nv_bfloat16* As = (p == 1) ? AloS : AhiS;
        const __nv_bfloat16* Bs = (p == 2) ? BlS : BhS;
        #pragma unroll
        for (int ks = 0; ks < 8; ks++) {
            int k0 = ks * 16;
            uint32_t af[2][4];
            #pragma unroll
            for (int mt = 0; mt < 2; mt++) {
                const __nv_bfloat16* base = As + (wr + mt * 16) * PITCH + k0;
                af[mt][0] = *(const uint32_t*)(base + g * PITCH + 2 * tig);
                af[mt][1] = *(const uint32_t*)(base + (g + 8) * PITCH + 2 * tig);
                af[mt][2] = *(const uint32_t*)(base + g * PITCH + 8 + 2 * tig);
                af[mt][3] = *(const uint32_t*)(base + (g + 8) * PITCH + 8 + 2 * tig);
            }
            #pragma unroll
            for (int nt = 0; nt < 8; nt++) {
                uint32_t bf[2];
                const __nv_bfloat16* nb = Bs + (wc + nt * 8 + g) * PITCH + k0;
                bf[0] = *(const uint32_t*)(nb + 2 * tig);
                bf[1] = *(const uint32_t*)(nb + 8 + 2 * tig);
                mma16816(cacc[0][nt], af[0], bf);
                mma16816(cacc[1][nt], af[1], bf);
            }
        }
    }

    // epilogue
    #pragma unroll
    for (int mt = 0; mt < 2; mt++) {
        int row = r0 + wr + mt * 16 + g;
        #pragma unroll
        for (int nt = 0; nt < 8; nt++) {
            int col = wc + nt * 8 + 2 * tig;
            float b0 = biasS[col], b1 = biasS[col + 1];
            float v00 = cacc[mt][nt][0] + b0, v01 = cacc[mt][nt][1] + b1;
            float v10 = cacc[mt][nt][2] + b0, v11 = cacc[mt][nt][3] + b1;
            if (osel == 1) {
                if (row < NN)
                    *(float2*)(d_res0 + (size_t)row * HID + col) = make_float2(v00, v01);
                if (row + 8 < NN)
                    *(float2*)(d_res0 + (size_t)(row + 8) * HID + col) = make_float2(v10, v11);
            } else {
                if (row < NN)
                    *(__half2*)(d_hwh + (size_t)row * HID + col) =
                        __floats2half2_rn(v00, v01);
                if (row + 8 < NN)
                    *(__half2*)(d_hwh + (size_t)(row + 8) * HID + col) =
                        __floats2half2_rn(v10, v11);
            }
        }
    }
}

// ---------------- fused aggregate + bias + LN + residual + relu + mean-acc ----------------
__device__ __forceinline__ void acc_edge(float4& acc, float w, uint2 raw) {
    float2 f0 = __half22float2(*(__half2*)&raw.x);
    float2 f1 = __half22float2(*(__half2*)&raw.y);
    acc.x = fmaf(w, f0.x, acc.x);
    acc.y = fmaf(w, f0.y, acc.y);
    acc.z = fmaf(w, f1.x, acc.z);
    acc.w = fmaf(w, f1.y, acc.w);
}

__global__ __launch_bounds__(256) void agg_ln_k(
    const float* __restrict__ cb, const float* __restrict__ gam,
    const float* __restrict__ bet, int rsel, int osel, int first)
{
    int n = (blockIdx.x * 256 + threadIdx.x) >> 5;
    if (n >= NN) return;
    int lane = threadIdx.x & 31;
    const float* resid = (rsel == 0) ? d_res0 : (rsel == 1) ? d_curA : d_curB;
    float* outp = (osel == 1) ? d_curA : d_curB;
    const uint2* hw2 = (const uint2*)d_hwh;
    size_t loff = (size_t)lane;  // uint2 index within row (row = 32 uint2)

    float dn = d_dis[n];
    float sn = dn * dn;
    float4 acc = ((const float4*)cb)[lane];
    acc_edge(acc, sn, hw2[(size_t)n * 32 + loff]);

    int jb = d_rowptr[n], je = d_rowptr[n + 1];
    int j = jb;
    for (; j + 4 <= je; j += 4) {
        float2 a0 = d_adj[j];
        float2 a1 = d_adj[j + 1];
        float2 a2 = d_adj[j + 2];
        float2 a3 = d_adj[j + 3];
        uint2 r0 = hw2[(size_t)__float_as_int(a0.x) * 32 + loff];
        uint2 r1 = hw2[(size_t)__float_as_int(a1.x) * 32 + loff];
        uint2 r2 = hw2[(size_t)__float_as_int(a2.x) * 32 + loff];
        uint2 r3 = hw2[(size_t)__float_as_int(a3.x) * 32 + loff];
        acc_edge(acc, a0.y, r0);
        acc_edge(acc, a1.y, r1);
        acc_edge(acc, a2.y, r2);
        acc_edge(acc, a3.y, r3);
    }
    for (; j < je; j++) {
        float2 a = d_adj[j];
        acc_edge(acc, a.y, hw2[(size_t)__float_as_int(a.x) * 32 + loff]);
    }

    float ss = acc.x + acc.y + acc.z + acc.w;
    #pragma unroll
    for (int o = 16; o > 0; o >>= 1) ss += __shfl_xor_sync(0xffffffffu, ss, o);
    float mu = ss * (1.f / 128.f);
    float dx0 = acc.x - mu, dx1 = acc.y - mu, dx2 = acc.z - mu, dx3 = acc.w - mu;
    float q = dx0 * dx0 + dx1 * dx1 + dx2 * dx2 + dx3 * dx3;
    #pragma unroll
    for (int o = 16; o > 0; o >>= 1) q += __shfl_xor_sync(0xffffffffu, q, o);
    float rstd = rsqrtf(q * (1.f / 128.f) + 1e-5f);

    float4 gv = ((const float4*)gam)[lane];
    float4 bv = ((const float4*)bet)[lane];
    float4 rv = ((const float4*)resid)[(size_t)n * 32 + lane];
    float4 h;
    h.x = fmaxf(fmaf(gv.x, dx0 * rstd, bv.x) + rv.x, 0.f);
    h.y = fmaxf(fmaf(gv.y, dx1 * rstd, bv.y) + rv.y, 0.f);
    h.z = fmaxf(fmaf(gv.z, dx2 * rstd, bv.z) + rv.z, 0.f);
    h.w = fmaxf(fmaf(gv.w, dx3 * rstd, bv.w) + rv.w, 0.f);

    ((float4*)outp)[(size_t)n * 32 + lane] = h;
    float4* xm4 = (float4*)d_xm;
    if (first) {
        xm4[(size_t)n * 32 + lane] = h;
    } else {
        float4 t = xm4[(size_t)n * 32 + lane];
        t.x += h.x; t.y += h.y; t.z += h.z; t.w += h.w;
        xm4[(size_t)n * 32 + lane] = t;
    }
}

// ---------------- graph segment boundaries ----------------
__global__ void mark_k(const int* __restrict__ batch) {
    int n = blockIdx.x * blockDim.x + threadIdx.x;
    if (n >= NN) return;
    int b = batch[n];
    if (n == 0 || batch[n - 1] != b) atomicMin(&d_gstart[b], n);
}

__global__ __launch_bounds__(512) void fix_k() {
    __shared__ int s[520];
    int t = threadIdx.x;
    s[t] = d_gstart[t];
    if (t == 0) s[GG] = NN;
    __syncthreads();
    for (int o = 1; o <= GG; o <<= 1) {
        int v = s[t];
        int u = (t + o <= GG) ? s[t + o] : NN;
        __syncthreads();
        s[t] = min(v, u);
        __syncthreads();
    }
    d_gstart[t] = s[t];
}

// ---------------- pooling ----------------
__global__ __launch_bounds__(128) void pool_k() {
    int g = blockIdx.x, c = threadIdx.x;
    int s = d_gstart[g], e = d_gstart[g + 1];
    float sum = 0.f, mx = 0.f;
    for (int n = s; n < e; n++) {
        float v = d_xm[(size_t)n * HID + c] * 0.25f;
        sum += v;
        mx = fmaxf(mx, v);
    }
    int cnt = e - s;
    d_gmean[g * HID + c] = sum / (float)max(cnt, 1);
    d_gmaxv[g * HID + c] = mx;
}

// ---------------- head ----------------
__global__ __launch_bounds__(128) void head_k(
    const float* __restrict__ hW1, const float* __restrict__ hb1,
    const float* __restrict__ hW2, const float* __restrict__ hb2,
    float* __restrict__ out)
{
    __shared__ float gf[256];
    __shared__ float h1s[128];
    int g = blockIdx.x, t = threadIdx.x;
    gf[t] = d_gmean[g * HID + t];
    gf[128 + t] = d_gmaxv[g * HID + t];
    __syncthreads();
    float acc = hb1[t];
    #pragma unroll 8
    for (int k = 0; k < 256; k++) acc = fmaf(gf[k], hW1[k * HID + t], acc);
    h1s[t] = fmaxf(acc, 0.f);
    __syncthreads();
    if (t < NCLS) {
        float o = hb2[t];
        #pragma unroll 8
        for (int k = 0; k < 128; k++) o = fmaf(h1s[k], hW2[k * NCLS + t], o);
        out[g * NCLS + t] = o;
    }
}

// ---------------- launcher ----------------
extern "C" void kernel_launch(void* const* d_in, const int* in_sizes, int n_in,
                              void* d_out, int out_size) {
    const float* x     = (const float*)d_in[0];
    const int*   ei    = (const int*)d_in[1];
    const int*   batch = (const int*)d_in[2];
    const float* ea    = (const float*)d_in[3];
    const float* eeW1  = (const float*)d_in[4];
    const float* eeb1  = (const float*)d_in[5];
    const float* eeW2  = (const float*)d_in[6];
    const float* eeb2  = (const float*)d_in[7];
    const float* W[4]  = {(const float*)d_in[8],  (const float*)d_in[10],
                          (const float*)d_in[12], (const float*)d_in[14]};
    const float* cbp[4]= {(const float*)d_in[9],  (const float*)d_in[11],
                          (const float*)d_in[13], (const float*)d_in[15]};
    const float* gm[4] = {(const float*)d_in[16], (const float*)d_in[18],
                          (const float*)d_in[20], (const float*)d_in[22]};
    const float* be[4] = {(const float*)d_in[17], (const float*)d_in[19],
                          (const float*)d_in[21], (const float*)d_in[23]};
    const float* resW  = (const float*)d_in[24];
    const float* resB  = (const float*)d_in[25];
    const float* hW1   = (const float*)d_in[26];
    const float* hb1   = (const float*)d_in[27];
    const float* hW2   = (const float*)d_in[28];
    const float* hb2   = (const float*)d_in[29];
    float* out = (float*)d_out;

    cudaFuncSetAttribute(mma_gemm_k, cudaFuncAttributeMaxDynamicSharedMemorySize, SMEM_GEMM);

    const int nblkN = (NN + 255) / 256;
    const int nblkE = (EE + 255) / 256;
    const int tileG = (NN + 127) / 128;
    const int aggG  = (NN + 7) / 8;

    init_k<<<nblkN, 256>>>();
    edge_mlp_k<<<nblkE, 256>>>(ea, eeW1, eeb1, eeW2, eeb2, ei + EE);
    dis_k<<<nblkN, 256>>>();
    scan1_k<<<SCAN_BLOCKS, 1024>>>();
    scan2_k<<<1, 128>>>();
    scan3_k<<<SCAN_BLOCKS, 1024>>>();
    fill_k<<<nblkE, 256>>>(ei, ei + EE);
    prep_k<<<5, 128>>>(resW, W[0], W[1], W[2], W[3]);

    // residual projection for layer 0: x @ resW + resB -> d_res0
    mma_gemm_k<<<tileG, 256, SMEM_GEMM>>>(x, 0, 1, 0, IN_C, resB);
    // layer 0
    mma_gemm_k<<<tileG, 256, SMEM_GEMM>>>(x, 0, 0, 1, IN_C, nullptr);
    agg_ln_k<<<aggG, 256>>>(cbp[0], gm[0], be[0], 0, 1, 1);
    // layer 1
    mma_gemm_k<<<tileG, 256, SMEM_GEMM>>>(nullptr, 1, 0, 2, HID, nullptr);
    agg_ln_k<<<aggG, 256>>>(cbp[1], gm[1], be[1], 1, 2, 0);
    // layer 2
    mma_gemm_k<<<tileG, 256, SMEM_GEMM>>>(nullptr, 2, 0, 3, HID, nullptr);
    agg_ln_k<<<aggG, 256>>>(cbp[2], gm[2], be[2], 2, 1, 0);
    // layer 3
    mma_gemm_k<<<tileG, 256, SMEM_GEMM>>>(nullptr, 1, 0, 4, HID, nullptr);
    agg_ln_k<<<aggG, 256>>>(cbp[3], gm[3], be[3], 1, 2, 0);

    mark_k<<<nblkN, 256>>>(batch);
    fix_k<<<1, 512>>>();
    pool_k<<<GG, 128>>>();
    head_k<<<GG, 128>>>(hW1, hb1, hW2, hb2, out);
}

// round 6
// speedup vs baseline: 1.1839x; 1.0400x over previous
#include <cuda_runtime.h>
#include <cuda_bf16.h>
#include <cuda_fp16.h>
#include <math.h>
#include <stdint.h>

#define NN   100000
#define EE   1600000
#define GG   512
#define IN_C 96
#define HID  128
#define NCLS 100
#define SCAN_BLOCKS 98   // ceil(100000/1024)

// ---------------- scratch (device globals; no allocation) ----------------
__device__ float  d_ew[EE];
__device__ int    d_pos[EE];
__device__ int    d_cnt[NN];
__device__ int    d_rowptr[NN + 1];
__device__ int    d_bsum[SCAN_BLOCKS];
__device__ int    d_boff[SCAN_BLOCKS];
__device__ float2 d_adj[EE];            // packed (src as int bits, norm)
__device__ float  d_deg[NN];
__device__ float  d_dis[NN];
__device__ __half d_hwh[(size_t)NN * HID];   // GEMM output, fp16 (gather source)
__device__ float  d_curA[(size_t)NN * HID];
__device__ float  d_curB[(size_t)NN * HID];
__device__ float  d_res0[(size_t)NN * HID];
__device__ float  d_xm  [(size_t)NN * HID];
__device__ int    d_gstart[GG + 1];
__device__ float  d_gmean[GG * HID];
__device__ float  d_gmaxv[GG * HID];
// pre-split weights, n-major [128 n][128 k] bf16, hi and lo parts, 5 matrices
__device__ __nv_bfloat16 d_Bh[5 * 128 * 128];
__device__ __nv_bfloat16 d_Bl[5 * 128 * 128];
// edge-MLP W1 pre-split, n-major [128 n][16 k] (k 8..15 zero)
__device__ __nv_bfloat16 d_EBh[128 * 16];
__device__ __nv_bfloat16 d_EBl[128 * 16];

// ---------------- init ----------------
__global__ void init_k() {
    int i = blockIdx.x * blockDim.x + threadIdx.x;
    if (i < NN) { d_deg[i] = 1.0f; d_cnt[i] = 0; }
    if (i <= GG) d_gstart[i] = NN;
}

// ---------------- mma helper ----------------
__device__ __forceinline__ void mma16816(float* c, const uint32_t* a, const uint32_t* b) {
    asm volatile(
        "mma.sync.aligned.m16n8k16.row.col.f32.bf16.bf16.f32 "
        "{%0,%1,%2,%3}, {%4,%5,%6,%7}, {%8,%9}, {%0,%1,%2,%3};"
        : "+f"(c[0]), "+f"(c[1]), "+f"(c[2]), "+f"(c[3])
        : "r"(a[0]), "r"(a[1]), "r"(a[2]), "r"(a[3]), "r"(b[0]), "r"(b[1]));
}

__device__ __forceinline__ void split_bf16(float v, __nv_bfloat16& h, __nv_bfloat16& l) {
    h = __float2bfloat16_rn(v);
    l = __float2bfloat16_rn(v - __bfloat162float(h));
}

// ---------------- edge W1 prep ----------------
__global__ __launch_bounds__(128) void prep_e_k(const float* __restrict__ W1) {
    int n = threadIdx.x;
    for (int k = 0; k < 16; k++) {
        float v = (k < 8) ? W1[k * 128 + n] : 0.f;
        __nv_bfloat16 h, l;
        split_bf16(v, h, l);
        d_EBh[n * 16 + k] = h;
        d_EBl[n * 16 + k] = l;
    }
}

// ---------------- tensor-core edge MLP + softplus + deg/count (fused) ----------------
#define EPITCH 24
__global__ __launch_bounds__(256) void edge_mma_k(
    const float* __restrict__ ea, const float* __restrict__ b1,
    const float* __restrict__ W2, const float* __restrict__ b2v,
    const int* __restrict__ col)
{
    __shared__ __nv_bfloat16 Ah[128 * EPITCH];
    __shared__ __nv_bfloat16 Al[128 * EPITCH];
    __shared__ __nv_bfloat16 Bh[128 * EPITCH];
    __shared__ __nv_bfloat16 Bl[128 * EPITCH];
    __shared__ float b1s[128];
    __shared__ float W2s[128];
    __shared__ float part[128][2];

    int tid = threadIdx.x;
    int e0 = blockIdx.x * 128;

    if (tid < 128) { b1s[tid] = b1[tid]; W2s[tid] = W2[tid]; }

    // stage B
    for (int i = tid; i < 128 * 16; i += 256) {
        int n = i >> 4, k = i & 15;
        Bh[n * EPITCH + k] = d_EBh[i];
        Bl[n * EPITCH + k] = d_EBl[i];
    }
    // stage A: thread -> (edge, half); each loads 4 floats, splits, zeros upper k
    {
        int e = tid >> 1, half = tid & 1;
        float4 v = *(const float4*)(ea + (size_t)(e0 + e) * 8 + half * 4);
        __nv_bfloat16 h0, l0, h1, l1, h2, l2, h3, l3;
        split_bf16(v.x, h0, l0); split_bf16(v.y, h1, l1);
        split_bf16(v.z, h2, l2); split_bf16(v.w, h3, l3);
        __nv_bfloat16* ah = Ah + e * EPITCH + half * 4;
        __nv_bfloat16* al = Al + e * EPITCH + half * 4;
        ah[0] = h0; ah[1] = h1; ah[2] = h2; ah[3] = h3;
        al[0] = l0; al[1] = l1; al[2] = l2; al[3] = l3;
        // zero k = 8..15
        __nv_bfloat16 z = __float2bfloat16_rn(0.f);
        __nv_bfloat16* zh = Ah + e * EPITCH + 8 + half * 4;
        __nv_bfloat16* zl = Al + e * EPITCH + 8 + half * 4;
        zh[0] = z; zh[1] = z; zh[2] = z; zh[3] = z;
        zl[0] = z; zl[1] = z; zl[2] = z; zl[3] = z;
    }
    __syncthreads();

    int wid = tid >> 5, lane = tid & 31;
    int g = lane >> 2, tig = lane & 3;
    int wr = (wid & 3) * 32;
    int wc = (wid >> 2) * 64;

    float cacc[2][8][4];
    #pragma unroll
    for (int mt = 0; mt < 2; mt++)
        #pragma unroll
        for (int nt = 0; nt < 8; nt++)
            #pragma unroll
            for (int q = 0; q < 4; q++) cacc[mt][nt][q] = 0.f;

    #pragma unroll
    for (int p = 0; p < 3; p++) {
        const __nv_bfloat16* As = (p == 1) ? Al : Ah;
        const __nv_bfloat16* Bs = (p == 2) ? Bl : Bh;
        uint32_t af[2][4];
        #pragma unroll
        for (int mt = 0; mt < 2; mt++) {
            const __nv_bfloat16* base = As + (wr + mt * 16) * EPITCH;
            af[mt][0] = *(const uint32_t*)(base + g * EPITCH + 2 * tig);
            af[mt][1] = *(const uint32_t*)(base + (g + 8) * EPITCH + 2 * tig);
            af[mt][2] = *(const uint32_t*)(base + g * EPITCH + 8 + 2 * tig);
            af[mt][3] = *(const uint32_t*)(base + (g + 8) * EPITCH + 8 + 2 * tig);
        }
        #pragma unroll
        for (int nt = 0; nt < 8; nt++) {
            uint32_t bf[2];
            const __nv_bfloat16* nb = Bs + (wc + nt * 8 + g) * EPITCH;
            bf[0] = *(const uint32_t*)(nb + 2 * tig);
            bf[1] = *(const uint32_t*)(nb + 8 + 2 * tig);
            mma16816(cacc[0][nt], af[0], bf);
            mma16816(cacc[1][nt], af[1], bf);
        }
    }

    // fused relu + dot(W2): per-thread partial over its 16 cols, rows g and g+8 per mt
    #pragma unroll
    for (int mt = 0; mt < 2; mt++) {
        float s0 = 0.f, s8 = 0.f;
        #pragma unroll
        for (int nt = 0; nt < 8; nt++) {
            int c = wc + nt * 8 + 2 * tig;
            float w0 = W2s[c], w1 = W2s[c + 1];
            float bb0 = b1s[c], bb1 = b1s[c + 1];
            s0 = fmaf(fmaxf(cacc[mt][nt][0] + bb0, 0.f), w0, s0);
            s0 = fmaf(fmaxf(cacc[mt][nt][1] + bb1, 0.f), w1, s0);
            s8 = fmaf(fmaxf(cacc[mt][nt][2] + bb0, 0.f), w0, s8);
            s8 = fmaf(fmaxf(cacc[mt][nt][3] + bb1, 0.f), w1, s8);
        }
        // reduce across tig (lane bits 0-1)
        s0 += __shfl_xor_sync(0xffffffffu, s0, 1);
        s0 += __shfl_xor_sync(0xffffffffu, s0, 2);
        s8 += __shfl_xor_sync(0xffffffffu, s8, 1);
        s8 += __shfl_xor_sync(0xffffffffu, s8, 2);
        if (tig == 0) {
            int wn = wid >> 2;
            part[wr + mt * 16 + g][wn] = s0;
            part[wr + mt * 16 + g + 8][wn] = s8;
        }
    }
    __syncthreads();

    if (tid < 128) {
        int e = e0 + tid;
        float x = part[tid][0] + part[tid][1] + b2v[0];
        float sp = (x > 15.f) ? x : log1pf(expf(x));
        float ew = sp + 1e-4f;
        d_ew[e] = ew;
        int c = col[e];
        d_pos[e] = atomicAdd(&d_cnt[c], 1);
        atomicAdd(&d_deg[c], ew);
    }
}

__global__ void dis_k() {
    int i = blockIdx.x * blockDim.x + threadIdx.x;
    if (i < NN) d_dis[i] = rsqrtf(d_deg[i]);
}

// ---------------- hierarchical scan ----------------
__global__ __launch_bounds__(1024) void scan1_k() {
    __shared__ int wsum[32];
    int tid = threadIdx.x, lane = tid & 31, wid = tid >> 5;
    int i = blockIdx.x * 1024 + tid;
    int v = (i < NN) ? d_cnt[i] : 0;
    int s = v;
    #pragma unroll
    for (int o = 1; o < 32; o <<= 1) {
        int t = __shfl_up_sync(0xffffffffu, s, o);
        if (lane >= o) s += t;
    }
    if (lane == 31) wsum[wid] = s;
    __syncthreads();
    if (wid == 0) {
        int ws = wsum[lane];
        #pragma unroll
        for (int o = 1; o < 32; o <<= 1) {
            int t = __shfl_up_sync(0xffffffffu, ws, o);
            if (lane >= o) ws += t;
        }
        wsum[lane] = ws;
    }
    __syncthreads();
    int incl = s + ((wid > 0) ? wsum[wid - 1] : 0);
    if (i < NN) d_rowptr[i + 1] = incl;
    if (tid == 1023) d_bsum[blockIdx.x] = incl;
}

__global__ __launch_bounds__(128) void scan2_k() {
    int tid = threadIdx.x, lane = tid & 31, wid = tid >> 5;
    __shared__ int wsum[4];
    int v = (tid < SCAN_BLOCKS) ? d_bsum[tid] : 0;
    int s = v;
    #pragma unroll
    for (int o = 1; o < 32; o <<= 1) {
        int t = __shfl_up_sync(0xffffffffu, s, o);
        if (lane >= o) s += t;
    }
    if (lane == 31) wsum[wid] = s;
    __syncthreads();
    int add = 0;
    for (int w = 0; w < 4; w++) if (w < wid) add += wsum[w];
    if (tid < SCAN_BLOCKS) d_boff[tid] = s + add - v;
}

__global__ __launch_bounds__(1024) void scan3_k() {
    int i = blockIdx.x * 1024 + threadIdx.x;
    if (i < NN) d_rowptr[i + 1] += d_boff[blockIdx.x];
    if (i == 0) d_rowptr[0] = 0;
}

// ---------------- fill CSR (packed src+norm) ----------------
__global__ void fill_k(const int* __restrict__ row, const int* __restrict__ col) {
    int e = blockIdx.x * blockDim.x + threadIdx.x;
    if (e >= EE) return;
    int r = row[e], c = col[e];
    int j = d_rowptr[c] + d_pos[e];
    float2 v;
    v.x = __int_as_float(r);
    v.y = d_dis[r] * d_ew[e] * d_dis[c];
    d_adj[j] = v;
}

// ---------------- weight prep: split fp32 -> bf16 hi/lo, n-major [n][k] ----------------
__global__ __launch_bounds__(128) void prep_k(
    const float* __restrict__ resW, const float* __restrict__ W0,
    const float* __restrict__ W1, const float* __restrict__ W2,
    const float* __restrict__ W3)
{
    int m = blockIdx.x, n = threadIdx.x;
    const float* W; int K;
    switch (m) {
        case 0: W = resW; K = 96; break;
        case 1: W = W0;   K = 96; break;
        case 2: W = W1;   K = 128; break;
        case 3: W = W2;   K = 128; break;
        default: W = W3;  K = 128; break;
    }
    __nv_bfloat16* bh = d_Bh + (size_t)m * 16384 + (size_t)n * 128;
    __nv_bfloat16* bl = d_Bl + (size_t)m * 16384 + (size_t)n * 128;
    for (int k = 0; k < 128; k++) {
        float v = (k < K) ? W[(size_t)k * HID + n] : 0.f;
        __nv_bfloat16 h, l;
        split_bf16(v, h, l);
        bh[k] = h;
        bl[k] = l;
    }
}

// ---------------- HMMA bf16 split GEMM: C[M,128] = A[M,K] @ W + (bias) ----------------
#define PITCH 136
#define BUFSZ (128 * PITCH)
#define SMEM_GEMM (4 * BUFSZ * 2)

// asel: 0 -> Ain, 1 -> d_curA, 2 -> d_curB ; osel: 0 -> d_hwh (half), 1 -> d_res0 (f32)
__global__ __launch_bounds__(256) void mma_gemm_k(
    const float* __restrict__ Ain, int asel, int osel, int mat,
    int lda, const float* __restrict__ bias)
{
    extern __shared__ __nv_bfloat16 sm[];
    __nv_bfloat16* AhiS = sm;
    __nv_bfloat16* AloS = sm + BUFSZ;
    __nv_bfloat16* BhS  = sm + 2 * BUFSZ;
    __nv_bfloat16* BlS  = sm + 3 * BUFSZ;
    __shared__ float biasS[128];

    const float* A = (asel == 1) ? d_curA : (asel == 2) ? d_curB : Ain;
    int tid = threadIdx.x;
    int r0 = blockIdx.x * 128;

    if (tid < 128) biasS[tid] = bias ? bias[tid] : 0.f;

    // stage A (fp32 -> hi/lo bf16)
    {
        int rr = tid >> 5;           // 0..7
        int cc = (tid & 31) * 4;     // 0..124
        #pragma unroll 4
        for (int it = 0; it < 16; it++) {
            int r = it * 8 + rr;
            int R = r0 + r;
            float4 v = make_float4(0.f, 0.f, 0.f, 0.f);
            if (R < NN && cc < lda)
                v = *(const float4*)(A + (size_t)R * lda + cc);
            __nv_bfloat16 h0, l0, h1, l1, h2, l2, h3, l3;
            split_bf16(v.x, h0, l0); split_bf16(v.y, h1, l1);
            split_bf16(v.z, h2, l2); split_bf16(v.w, h3, l3);
            uint2 ph, pl;
            ph.x = ((uint32_t)__bfloat16_as_ushort(h1) << 16) | __bfloat16_as_ushort(h0);
            ph.y = ((uint32_t)__bfloat16_as_ushort(h3) << 16) | __bfloat16_as_ushort(h2);
            pl.x = ((uint32_t)__bfloat16_as_ushort(l1) << 16) | __bfloat16_as_ushort(l0);
            pl.y = ((uint32_t)__bfloat16_as_ushort(l3) << 16) | __bfloat16_as_ushort(l2);
            *(uint2*)(AhiS + r * PITCH + cc) = ph;
            *(uint2*)(AloS + r * PITCH + cc) = pl;
        }
    }
    // stage B (already split, n-major)
    {
        int rr = tid >> 5;
        int cc = (tid & 31) * 4;
        const __nv_bfloat16* gh = d_Bh + (size_t)mat * 16384;
        const __nv_bfloat16* gl = d_Bl + (size_t)mat * 16384;
        #pragma unroll 4
        for (int it = 0; it < 16; it++) {
            int n = it * 8 + rr;
            *(uint2*)(BhS + n * PITCH + cc) = *(const uint2*)(gh + n * 128 + cc);
            *(uint2*)(BlS + n * PITCH + cc) = *(const uint2*)(gl + n * 128 + cc);
        }
    }
    __syncthreads();

    int wid = tid >> 5, lane = tid & 31;
    int g = lane >> 2, tig = lane & 3;
    int wr = (wid & 3) * 32;          // warp M base
    int wc = (wid >> 2) * 64;         // warp N base

    float cacc[2][8][4];
    #pragma unroll
    for (int mt = 0; mt < 2; mt++)
        #pragma unroll
        for (int nt = 0; nt < 8; nt++)
            #pragma unroll
            for (int q = 0; q < 4; q++) cacc[mt][nt][q] = 0.f;

    #pragma unroll
    for (int p = 0; p < 3; p++) {
        const __nv_bfloat16* As = (p == 1) ? AloS : AhiS;
        const __nv_bfloat16* Bs = (p == 2) ? BlS : BhS;
        #pragma unroll
        for (int ks = 0; ks < 8; ks++) {
            int k0 = ks * 16;
            uint32_t af[2][4];
            #pragma unroll
            for (int mt = 0; mt < 2; mt++) {
                const __nv_bfloat16* base = As + (wr + mt * 16) * PITCH + k0;
                af[mt][0] = *(const uint32_t*)(base + g * PITCH + 2 * tig);
                af[mt][1] = *(const uint32_t*)(base + (g + 8) * PITCH + 2 * tig);
                af[mt][2] = *(const uint32_t*)(base + g * PITCH + 8 + 2 * tig);
                af[mt][3] = *(const uint32_t*)(base + (g + 8) * PITCH + 8 + 2 * tig);
            }
            #pragma unroll
            for (int nt = 0; nt < 8; nt++) {
                uint32_t bf[2];
                const __nv_bfloat16* nb = Bs + (wc + nt * 8 + g) * PITCH + k0;
                bf[0] = *(const uint32_t*)(nb + 2 * tig);
                bf[1] = *(const uint32_t*)(nb + 8 + 2 * tig);
                mma16816(cacc[0][nt], af[0], bf);
                mma16816(cacc[1][nt], af[1], bf);
            }
        }
    }

    // epilogue
    #pragma unroll
    for (int mt = 0; mt < 2; mt++) {
        int row = r0 + wr + mt * 16 + g;
        #pragma unroll
        for (int nt = 0; nt < 8; nt++) {
            int col = wc + nt * 8 + 2 * tig;
            float b0 = biasS[col], b1 = biasS[col + 1];
            float v00 = cacc[mt][nt][0] + b0, v01 = cacc[mt][nt][1] + b1;
            float v10 = cacc[mt][nt][2] + b0, v11 = cacc[mt][nt][3] + b1;
            if (osel == 1) {
                if (row < NN)
                    *(float2*)(d_res0 + (size_t)row * HID + col) = make_float2(v00, v01);
                if (row + 8 < NN)
                    *(float2*)(d_res0 + (size_t)(row + 8) * HID + col) = make_float2(v10, v11);
            } else {
                if (row < NN)
                    *(__half2*)(d_hwh + (size_t)row * HID + col) =
                        __floats2half2_rn(v00, v01);
                if (row + 8 < NN)
                    *(__half2*)(d_hwh + (size_t)(row + 8) * HID + col) =
                        __floats2half2_rn(v10, v11);
            }
        }
    }
}

// ---------------- fused aggregate + bias + LN + residual + relu + mean-acc ----------------
__device__ __forceinline__ void acc_edge(float4& acc, float w, uint2 raw) {
    float2 f0 = __half22float2(*(__half2*)&raw.x);
    float2 f1 = __half22float2(*(__half2*)&raw.y);
    acc.x = fmaf(w, f0.x, acc.x);
    acc.y = fmaf(w, f0.y, acc.y);
    acc.z = fmaf(w, f1.x, acc.z);
    acc.w = fmaf(w, f1.y, acc.w);
}

__global__ __launch_bounds__(256) void agg_ln_k(
    const float* __restrict__ cb, const float* __restrict__ gam,
    const float* __restrict__ bet, int rsel, int osel, int first)
{
    int n = (blockIdx.x * 256 + threadIdx.x) >> 5;
    if (n >= NN) return;
    int lane = threadIdx.x & 31;
    const float* resid = (rsel == 0) ? d_res0 : (rsel == 1) ? d_curA : d_curB;
    float* outp = (osel == 1) ? d_curA : d_curB;
    const uint2* hw2 = (const uint2*)d_hwh;
    size_t loff = (size_t)lane;

    float dn = d_dis[n];
    float sn = dn * dn;
    float4 acc = ((const float4*)cb)[lane];
    acc_edge(acc, sn, hw2[(size_t)n * 32 + loff]);

    int jb = d_rowptr[n], je = d_rowptr[n + 1];
    int j = jb;
    for (; j + 4 <= je; j += 4) {
        float2 a0 = d_adj[j];
        float2 a1 = d_adj[j + 1];
        float2 a2 = d_adj[j + 2];
        float2 a3 = d_adj[j + 3];
        uint2 r0 = hw2[(size_t)__float_as_int(a0.x) * 32 + loff];
        uint2 r1 = hw2[(size_t)__float_as_int(a1.x) * 32 + loff];
        uint2 r2 = hw2[(size_t)__float_as_int(a2.x) * 32 + loff];
        uint2 r3 = hw2[(size_t)__float_as_int(a3.x) * 32 + loff];
        acc_edge(acc, a0.y, r0);
        acc_edge(acc, a1.y, r1);
        acc_edge(acc, a2.y, r2);
        acc_edge(acc, a3.y, r3);
    }
    for (; j < je; j++) {
        float2 a = d_adj[j];
        acc_edge(acc, a.y, hw2[(size_t)__float_as_int(a.x) * 32 + loff]);
    }

    float ss = acc.x + acc.y + acc.z + acc.w;
    #pragma unroll
    for (int o = 16; o > 0; o >>= 1) ss += __shfl_xor_sync(0xffffffffu, ss, o);
    float mu = ss * (1.f / 128.f);
    float dx0 = acc.x - mu, dx1 = acc.y - mu, dx2 = acc.z - mu, dx3 = acc.w - mu;
    float q = dx0 * dx0 + dx1 * dx1 + dx2 * dx2 + dx3 * dx3;
    #pragma unroll
    for (int o = 16; o > 0; o >>= 1) q += __shfl_xor_sync(0xffffffffu, q, o);
    float rstd = rsqrtf(q * (1.f / 128.f) + 1e-5f);

    float4 gv = ((const float4*)gam)[lane];
    float4 bv = ((const float4*)bet)[lane];
    float4 rv = ((const float4*)resid)[(size_t)n * 32 + lane];
    float4 h;
    h.x = fmaxf(fmaf(gv.x, dx0 * rstd, bv.x) + rv.x, 0.f);
    h.y = fmaxf(fmaf(gv.y, dx1 * rstd, bv.y) + rv.y, 0.f);
    h.z = fmaxf(fmaf(gv.z, dx2 * rstd, bv.z) + rv.z, 0.f);
    h.w = fmaxf(fmaf(gv.w, dx3 * rstd, bv.w) + rv.w, 0.f);

    ((float4*)outp)[(size_t)n * 32 + lane] = h;
    float4* xm4 = (float4*)d_xm;
    if (first) {
        xm4[(size_t)n * 32 + lane] = h;
    } else {
        float4 t = xm4[(size_t)n * 32 + lane];
        t.x += h.x; t.y += h.y; t.z += h.z; t.w += h.w;
        xm4[(size_t)n * 32 + lane] = t;
    }
}

// ---------------- graph segment boundaries ----------------
__global__ void mark_k(const int* __restrict__ batch) {
    int n = blockIdx.x * blockDim.x + threadIdx.x;
    if (n >= NN) return;
    int b = batch[n];
    if (n == 0 || batch[n - 1] != b) atomicMin(&d_gstart[b], n);
}

__global__ __launch_bounds__(512) void fix_k() {
    __shared__ int s[520];
    int t = threadIdx.x;
    s[t] = d_gstart[t];
    if (t == 0) s[GG] = NN;
    __syncthreads();
    for (int o = 1; o <= GG; o <<= 1) {
        int v = s[t];
        int u = (t + o <= GG) ? s[t + o] : NN;
        __syncthreads();
        s[t] = min(v, u);
        __syncthreads();
    }
    d_gstart[t] = s[t];
}

// ---------------- pooling ----------------
__global__ __launch_bounds__(128) void pool_k() {
    int g = blockIdx.x, c = threadIdx.x;
    int s = d_gstart[g], e = d_gstart[g + 1];
    float sum = 0.f, mx = 0.f;
    for (int n = s; n < e; n++) {
        float v = d_xm[(size_t)n * HID + c] * 0.25f;
        sum += v;
        mx = fmaxf(mx, v);
    }
    int cnt = e - s;
    d_gmean[g * HID + c] = sum / (float)max(cnt, 1);
    d_gmaxv[g * HID + c] = mx;
}

// ---------------- head ----------------
__global__ __launch_bounds__(128) void head_k(
    const float* __restrict__ hW1, const float* __restrict__ hb1,
    const float* __restrict__ hW2, const float* __restrict__ hb2,
    float* __restrict__ out)
{
    __shared__ float gf[256];
    __shared__ float h1s[128];
    int g = blockIdx.x, t = threadIdx.x;
    gf[t] = d_gmean[g * HID + t];
    gf[128 + t] = d_gmaxv[g * HID + t];
    __syncthreads();
    float acc = hb1[t];
    #pragma unroll 8
    for (int k = 0; k < 256; k++) acc = fmaf(gf[k], hW1[k * HID + t], acc);
    h1s[t] = fmaxf(acc, 0.f);
    __syncthreads();
    if (t < NCLS) {
        float o = hb2[t];
        #pragma unroll 8
        for (int k = 0; k < 128; k++) o = fmaf(h1s[k], hW2[k * NCLS + t], o);
        out[g * NCLS + t] = o;
    }
}

// ---------------- launcher ----------------
extern "C" void kernel_launch(void* const* d_in, const int* in_sizes, int n_in,
                              void* d_out, int out_size) {
    const float* x     = (const float*)d_in[0];
    const int*   ei    = (const int*)d_in[1];
    const int*   batch = (const int*)d_in[2];
    const float* ea    = (const float*)d_in[3];
    const float* eeW1  = (const float*)d_in[4];
    const float* eeb1  = (const float*)d_in[5];
    const float* eeW2  = (const float*)d_in[6];
    const float* eeb2  = (const float*)d_in[7];
    const float* W[4]  = {(const float*)d_in[8],  (const float*)d_in[10],
                          (const float*)d_in[12], (const float*)d_in[14]};
    const float* cbp[4]= {(const float*)d_in[9],  (const float*)d_in[11],
                          (const float*)d_in[13], (const float*)d_in[15]};
    const float* gm[4] = {(const float*)d_in[16], (const float*)d_in[18],
                          (const float*)d_in[20], (const float*)d_in[22]};
    const float* be[4] = {(const float*)d_in[17], (const float*)d_in[19],
                          (const float*)d_in[21], (const float*)d_in[23]};
    const float* resW  = (const float*)d_in[24];
    const float* resB  = (const float*)d_in[25];
    const float* hW1   = (const float*)d_in[26];
    const float* hb1   = (const float*)d_in[27];
    const float* hW2   = (const float*)d_in[28];
    const float* hb2   = (const float*)d_in[29];
    float* out = (float*)d_out;

    cudaFuncSetAttribute(mma_gemm_k, cudaFuncAttributeMaxDynamicSharedMemorySize, SMEM_GEMM);

    const int nblkN = (NN + 255) / 256;
    const int nblkE = (EE + 255) / 256;
    const int tileG = (NN + 127) / 128;
    const int aggG  = (NN + 7) / 8;
    const int edgeG = EE / 128;   // 12500, exact

    init_k<<<nblkN, 256>>>();
    prep_e_k<<<1, 128>>>(eeW1);
    prep_k<<<5, 128>>>(resW, W[0], W[1], W[2], W[3]);
    edge_mma_k<<<edgeG, 256>>>(ea, eeb1, eeW2, eeb2, ei + EE);
    dis_k<<<nblkN, 256>>>();
    scan1_k<<<SCAN_BLOCKS, 1024>>>();
    scan2_k<<<1, 128>>>();
    scan3_k<<<SCAN_BLOCKS, 1024>>>();
    fill_k<<<nblkE, 256>>>(ei, ei + EE);

    // residual projection for layer 0: x @ resW + resB -> d_res0
    mma_gemm_k<<<tileG, 256, SMEM_GEMM>>>(x, 0, 1, 0, IN_C, resB);
    // layer 0
    mma_gemm_k<<<tileG, 256, SMEM_GEMM>>>(x, 0, 0, 1, IN_C, nullptr);
    agg_ln_k<<<aggG, 256>>>(cbp[0], gm[0], be[0], 0, 1, 1);
    // layer 1
    mma_gemm_k<<<tileG, 256, SMEM_GEMM>>>(nullptr, 1, 0, 2, HID, nullptr);
    agg_ln_k<<<aggG, 256>>>(cbp[1], gm[1], be[1], 1, 2, 0);
    // layer 2
    mma_gemm_k<<<tileG, 256, SMEM_GEMM>>>(nullptr, 2, 0, 3, HID, nullptr);
    agg_ln_k<<<aggG, 256>>>(cbp[2], gm[2], be[2], 2, 1, 0);
    // layer 3
    mma_gemm_k<<<tileG, 256, SMEM_GEMM>>>(nullptr, 1, 0, 4, HID, nullptr);
    agg_ln_k<<<aggG, 256>>>(cbp[3], gm[3], be[3], 1, 2, 0);

    mark_k<<<nblkN, 256>>>(batch);
    fix_k<<<1, 512>>>();
    pool_k<<<GG, 128>>>();
    head_k<<<GG, 128>>>(hW1, hb1, hW2, hb2, out);
}

// round 7
// speedup vs baseline: 1.2570x; 1.0617x over previous
#include <cuda_runtime.h>
#include <cuda_bf16.h>
#include <cuda_fp16.h>
#include <math.h>
#include <stdint.h>

#define NN   100000
#define EE   1600000
#define GG   512
#define IN_C 96
#define HID  128
#define NCLS 100
#define SCAN_BLOCKS 98   // ceil(100000/1024)
#define ETILES 4         // edge tiles per block (512 edges)

// ---------------- scratch (device globals; no allocation) ----------------
__device__ float  d_ew[EE];
__device__ int    d_pos[EE];
__device__ int    d_cnt[NN];
__device__ int    d_rowptr[NN + 1];
__device__ int    d_bsum[SCAN_BLOCKS];
__device__ int    d_boff[SCAN_BLOCKS];
__device__ float2 d_adj[EE];            // packed (src as int bits, norm)
__device__ float  d_deg[NN];
__device__ float  d_dis[NN];
__device__ __half d_hwh[(size_t)NN * HID];   // GEMM output, fp16 (gather source)
__device__ float  d_curA[(size_t)NN * HID];
__device__ float  d_curB[(size_t)NN * HID];
__device__ float  d_res0[(size_t)NN * HID];
__device__ float  d_xm  [(size_t)NN * HID];
__device__ int    d_gstart[GG + 1];
__device__ float  d_gmean[GG * HID];
__device__ float  d_gmaxv[GG * HID];
// pre-split weights, n-major [128 n][128 k] bf16, hi and lo parts, 5 matrices
__device__ __nv_bfloat16 d_Bh[5 * 128 * 128];
__device__ __nv_bfloat16 d_Bl[5 * 128 * 128];
// edge-MLP W1 pre-split, n-major [128 n][16 k] (k 8..15 zero)
__device__ __nv_bfloat16 d_EBh[128 * 16];
__device__ __nv_bfloat16 d_EBl[128 * 16];

// ---------------- init ----------------
__global__ void init_k() {
    int i = blockIdx.x * blockDim.x + threadIdx.x;
    if (i < NN) { d_deg[i] = 1.0f; d_cnt[i] = 0; }
    if (i <= GG) d_gstart[i] = NN;
}

// ---------------- mma helper ----------------
__device__ __forceinline__ void mma16816(float* c, const uint32_t* a, const uint32_t* b) {
    asm volatile(
        "mma.sync.aligned.m16n8k16.row.col.f32.bf16.bf16.f32 "
        "{%0,%1,%2,%3}, {%4,%5,%6,%7}, {%8,%9}, {%0,%1,%2,%3};"
        : "+f"(c[0]), "+f"(c[1]), "+f"(c[2]), "+f"(c[3])
        : "r"(a[0]), "r"(a[1]), "r"(a[2]), "r"(a[3]), "r"(b[0]), "r"(b[1]));
}

__device__ __forceinline__ void split_bf16(float v, __nv_bfloat16& h, __nv_bfloat16& l) {
    h = __float2bfloat16_rn(v);
    l = __float2bfloat16_rn(v - __bfloat162float(h));
}

// ---------------- edge W1 prep ----------------
__global__ __launch_bounds__(128) void prep_e_k(const float* __restrict__ W1) {
    int n = threadIdx.x;
    for (int k = 0; k < 16; k++) {
        float v = (k < 8) ? W1[k * 128 + n] : 0.f;
        __nv_bfloat16 h, l;
        split_bf16(v, h, l);
        d_EBh[n * 16 + k] = h;
        d_EBl[n * 16 + k] = l;
    }
}

// ---------------- tensor-core edge MLP + softplus + deg/count (fused, multi-tile) ----------------
#define EPITCH 24
__global__ __launch_bounds__(256) void edge_mma_k(
    const float* __restrict__ ea, const float* __restrict__ b1,
    const float* __restrict__ W2, const float* __restrict__ b2v,
    const int* __restrict__ col)
{
    __shared__ __nv_bfloat16 Ah[128 * EPITCH];
    __shared__ __nv_bfloat16 Al[128 * EPITCH];
    __shared__ __nv_bfloat16 Bh[128 * EPITCH];
    __shared__ __nv_bfloat16 Bl[128 * EPITCH];
    __shared__ float b1s[128];
    __shared__ float W2s[128];
    __shared__ float part[128][2];

    int tid = threadIdx.x;
    int eb = blockIdx.x * (128 * ETILES);

    if (tid < 128) { b1s[tid] = b1[tid]; W2s[tid] = W2[tid]; }

    // stage B once per block
    for (int i = tid; i < 128 * 16; i += 256) {
        int n = i >> 4, k = i & 15;
        Bh[n * EPITCH + k] = d_EBh[i];
        Bl[n * EPITCH + k] = d_EBl[i];
    }
    // zero upper-k region of A once (k 8..15 never rewritten)
    {
        int e = tid >> 1, half = tid & 1;
        __nv_bfloat16 z = __float2bfloat16_rn(0.f);
        __nv_bfloat16* zh = Ah + e * EPITCH + 8 + half * 4;
        __nv_bfloat16* zl = Al + e * EPITCH + 8 + half * 4;
        zh[0] = z; zh[1] = z; zh[2] = z; zh[3] = z;
        zl[0] = z; zl[1] = z; zl[2] = z; zl[3] = z;
    }

    int wid = tid >> 5, lane = tid & 31;
    int g = lane >> 2, tig = lane & 3;
    int wr = (wid & 3) * 32;
    int wc = (wid >> 2) * 64;
    int eS = tid >> 1, half = tid & 1;   // staging coords

    for (int t = 0; t < ETILES; t++) {
        int e0 = eb + t * 128;
        // stage A tile
        {
            float4 v = *(const float4*)(ea + (size_t)(e0 + eS) * 8 + half * 4);
            __nv_bfloat16 h0, l0, h1, l1, h2, l2, h3, l3;
            split_bf16(v.x, h0, l0); split_bf16(v.y, h1, l1);
            split_bf16(v.z, h2, l2); split_bf16(v.w, h3, l3);
            __nv_bfloat16* ah = Ah + eS * EPITCH + half * 4;
            __nv_bfloat16* al = Al + eS * EPITCH + half * 4;
            ah[0] = h0; ah[1] = h1; ah[2] = h2; ah[3] = h3;
            al[0] = l0; al[1] = l1; al[2] = l2; al[3] = l3;
        }
        __syncthreads();

        float cacc[2][8][4];
        #pragma unroll
        for (int mt = 0; mt < 2; mt++)
            #pragma unroll
            for (int nt = 0; nt < 8; nt++)
                #pragma unroll
                for (int q = 0; q < 4; q++) cacc[mt][nt][q] = 0.f;

        #pragma unroll
        for (int p = 0; p < 3; p++) {
            const __nv_bfloat16* As = (p == 1) ? Al : Ah;
            const __nv_bfloat16* Bs = (p == 2) ? Bl : Bh;
            uint32_t af[2][4];
            #pragma unroll
            for (int mt = 0; mt < 2; mt++) {
                const __nv_bfloat16* base = As + (wr + mt * 16) * EPITCH;
                af[mt][0] = *(const uint32_t*)(base + g * EPITCH + 2 * tig);
                af[mt][1] = *(const uint32_t*)(base + (g + 8) * EPITCH + 2 * tig);
                af[mt][2] = *(const uint32_t*)(base + g * EPITCH + 8 + 2 * tig);
                af[mt][3] = *(const uint32_t*)(base + (g + 8) * EPITCH + 8 + 2 * tig);
            }
            #pragma unroll
            for (int nt = 0; nt < 8; nt++) {
                uint32_t bf[2];
                const __nv_bfloat16* nb = Bs + (wc + nt * 8 + g) * EPITCH;
                bf[0] = *(const uint32_t*)(nb + 2 * tig);
                bf[1] = *(const uint32_t*)(nb + 8 + 2 * tig);
                mma16816(cacc[0][nt], af[0], bf);
                mma16816(cacc[1][nt], af[1], bf);
            }
        }

        // fused relu + dot(W2)
        #pragma unroll
        for (int mt = 0; mt < 2; mt++) {
            float s0 = 0.f, s8 = 0.f;
            #pragma unroll
            for (int nt = 0; nt < 8; nt++) {
                int c = wc + nt * 8 + 2 * tig;
                float w0 = W2s[c], w1 = W2s[c + 1];
                float bb0 = b1s[c], bb1 = b1s[c + 1];
                s0 = fmaf(fmaxf(cacc[mt][nt][0] + bb0, 0.f), w0, s0);
                s0 = fmaf(fmaxf(cacc[mt][nt][1] + bb1, 0.f), w1, s0);
                s8 = fmaf(fmaxf(cacc[mt][nt][2] + bb0, 0.f), w0, s8);
                s8 = fmaf(fmaxf(cacc[mt][nt][3] + bb1, 0.f), w1, s8);
            }
            s0 += __shfl_xor_sync(0xffffffffu, s0, 1);
            s0 += __shfl_xor_sync(0xffffffffu, s0, 2);
            s8 += __shfl_xor_sync(0xffffffffu, s8, 1);
            s8 += __shfl_xor_sync(0xffffffffu, s8, 2);
            if (tig == 0) {
                int wn = wid >> 2;
                part[wr + mt * 16 + g][wn] = s0;
                part[wr + mt * 16 + g + 8][wn] = s8;
            }
        }
        __syncthreads();

        if (tid < 128) {
            int e = e0 + tid;
            float x = part[tid][0] + part[tid][1] + b2v[0];
            float sp = (x > 15.f) ? x : log1pf(expf(x));
            float ew = sp + 1e-4f;
            d_ew[e] = ew;
            int c = col[e];
            d_pos[e] = atomicAdd(&d_cnt[c], 1);
            atomicAdd(&d_deg[c], ew);
        }
        __syncthreads();
    }
}

__global__ void dis_k() {
    int i = blockIdx.x * blockDim.x + threadIdx.x;
    if (i < NN) d_dis[i] = rsqrtf(d_deg[i]);
}

// ---------------- hierarchical scan ----------------
__global__ __launch_bounds__(1024) void scan1_k() {
    __shared__ int wsum[32];
    int tid = threadIdx.x, lane = tid & 31, wid = tid >> 5;
    int i = blockIdx.x * 1024 + tid;
    int v = (i < NN) ? d_cnt[i] : 0;
    int s = v;
    #pragma unroll
    for (int o = 1; o < 32; o <<= 1) {
        int t = __shfl_up_sync(0xffffffffu, s, o);
        if (lane >= o) s += t;
    }
    if (lane == 31) wsum[wid] = s;
    __syncthreads();
    if (wid == 0) {
        int ws = wsum[lane];
        #pragma unroll
        for (int o = 1; o < 32; o <<= 1) {
            int t = __shfl_up_sync(0xffffffffu, ws, o);
            if (lane >= o) ws += t;
        }
        wsum[lane] = ws;
    }
    __syncthreads();
    int incl = s + ((wid > 0) ? wsum[wid - 1] : 0);
    if (i < NN) d_rowptr[i + 1] = incl;
    if (tid == 1023) d_bsum[blockIdx.x] = incl;
}

__global__ __launch_bounds__(128) void scan2_k() {
    int tid = threadIdx.x, lane = tid & 31, wid = tid >> 5;
    __shared__ int wsum[4];
    int v = (tid < SCAN_BLOCKS) ? d_bsum[tid] : 0;
    int s = v;
    #pragma unroll
    for (int o = 1; o < 32; o <<= 1) {
        int t = __shfl_up_sync(0xffffffffu, s, o);
        if (lane >= o) s += t;
    }
    if (lane == 31) wsum[wid] = s;
    __syncthreads();
    int add = 0;
    for (int w = 0; w < 4; w++) if (w < wid) add += wsum[w];
    if (tid < SCAN_BLOCKS) d_boff[tid] = s + add - v;
}

__global__ __launch_bounds__(1024) void scan3_k() {
    int i = blockIdx.x * 1024 + threadIdx.x;
    if (i < NN) d_rowptr[i + 1] += d_boff[blockIdx.x];
    if (i == 0) d_rowptr[0] = 0;
}

// ---------------- fill CSR (packed src+norm) ----------------
__global__ void fill_k(const int* __restrict__ row, const int* __restrict__ col) {
    int e = blockIdx.x * blockDim.x + threadIdx.x;
    if (e >= EE) return;
    int r = row[e], c = col[e];
    int j = d_rowptr[c] + d_pos[e];
    float2 v;
    v.x = __int_as_float(r);
    v.y = d_dis[r] * d_ew[e] * d_dis[c];
    d_adj[j] = v;
}

// ---------------- weight prep: split fp32 -> bf16 hi/lo, n-major [n][k] ----------------
__global__ __launch_bounds__(128) void prep_k(
    const float* __restrict__ resW, const float* __restrict__ W0,
    const float* __restrict__ W1, const float* __restrict__ W2,
    const float* __restrict__ W3)
{
    int m = blockIdx.x, n = threadIdx.x;
    const float* W; int K;
    switch (m) {
        case 0: W = resW; K = 96; break;
        case 1: W = W0;   K = 96; break;
        case 2: W = W1;   K = 128; break;
        case 3: W = W2;   K = 128; break;
        default: W = W3;  K = 128; break;
    }
    __nv_bfloat16* bh = d_Bh + (size_t)m * 16384 + (size_t)n * 128;
    __nv_bfloat16* bl = d_Bl + (size_t)m * 16384 + (size_t)n * 128;
    for (int k = 0; k < 128; k++) {
        float v = (k < K) ? W[(size_t)k * HID + n] : 0.f;
        __nv_bfloat16 h, l;
        split_bf16(v, h, l);
        bh[k] = h;
        bl[k] = l;
    }
}

// ---------------- HMMA bf16 split GEMM: C[M,128] = A[M,K] @ W + (bias) ----------------
#define PITCH 136
#define BUFSZ (128 * PITCH)
#define SMEM_GEMM (4 * BUFSZ * 2)

// asel: 0 -> Ain, 1 -> d_curA, 2 -> d_curB
// mat/osel pass 1; mat2/osel2 optional second pass reusing staged A (mat2 < 0 -> skip)
// osel: 0 -> d_hwh (half), 1 -> d_res0 (f32)
__global__ __launch_bounds__(256) void mma_gemm_k(
    const float* __restrict__ Ain, int asel, int osel, int mat,
    int lda, const float* __restrict__ bias,
    int osel2, int mat2, const float* __restrict__ bias2)
{
    extern __shared__ __nv_bfloat16 sm[];
    __nv_bfloat16* AhiS = sm;
    __nv_bfloat16* AloS = sm + BUFSZ;
    __nv_bfloat16* BhS  = sm + 2 * BUFSZ;
    __nv_bfloat16* BlS  = sm + 3 * BUFSZ;
    __shared__ float biasS[128];

    const float* A = (asel == 1) ? d_curA : (asel == 2) ? d_curB : Ain;
    int tid = threadIdx.x;
    int r0 = blockIdx.x * 128;

    // stage A (fp32 -> hi/lo bf16) once
    {
        int rr = tid >> 5;           // 0..7
        int cc = (tid & 31) * 4;     // 0..124
        #pragma unroll 4
        for (int it = 0; it < 16; it++) {
            int r = it * 8 + rr;
            int R = r0 + r;
            float4 v = make_float4(0.f, 0.f, 0.f, 0.f);
            if (R < NN && cc < lda)
                v = *(const float4*)(A + (size_t)R * lda + cc);
            __nv_bfloat16 h0, l0, h1, l1, h2, l2, h3, l3;
            split_bf16(v.x, h0, l0); split_bf16(v.y, h1, l1);
            split_bf16(v.z, h2, l2); split_bf16(v.w, h3, l3);
            uint2 ph, pl;
            ph.x = ((uint32_t)__bfloat16_as_ushort(h1) << 16) | __bfloat16_as_ushort(h0);
            ph.y = ((uint32_t)__bfloat16_as_ushort(h3) << 16) | __bfloat16_as_ushort(h2);
            pl.x = ((uint32_t)__bfloat16_as_ushort(l1) << 16) | __bfloat16_as_ushort(l0);
            pl.y = ((uint32_t)__bfloat16_as_ushort(l3) << 16) | __bfloat16_as_ushort(l2);
            *(uint2*)(AhiS + r * PITCH + cc) = ph;
            *(uint2*)(AloS + r * PITCH + cc) = pl;
        }
    }

    int wid = tid >> 5, lane = tid & 31;
    int g = lane >> 2, tig = lane & 3;
    int wr = (wid & 3) * 32;          // warp M base
    int wc = (wid >> 2) * 64;         // warp N base

    int curMat = mat, curOsel = osel;
    const float* curBias = bias;

    for (int pass = 0; pass < 2; pass++) {
        if (pass == 1) {
            if (mat2 < 0) break;
            curMat = mat2; curOsel = osel2; curBias = bias2;
            __syncthreads();   // ensure all reads of previous B done
        }
        // stage B (already split, n-major)
        {
            int rr = tid >> 5;
            int cc = (tid & 31) * 4;
            const __nv_bfloat16* gh = d_Bh + (size_t)curMat * 16384;
            const __nv_bfloat16* gl = d_Bl + (size_t)curMat * 16384;
            #pragma unroll 4
            for (int it = 0; it < 16; it++) {
                int n = it * 8 + rr;
                *(uint2*)(BhS + n * PITCH + cc) = *(const uint2*)(gh + n * 128 + cc);
                *(uint2*)(BlS + n * PITCH + cc) = *(const uint2*)(gl + n * 128 + cc);
            }
        }
        if (tid < 128) biasS[tid] = curBias ? curBias[tid] : 0.f;
        __syncthreads();

        float cacc[2][8][4];
        #pragma unroll
        for (int mt = 0; mt < 2; mt++)
            #pragma unroll
            for (int nt = 0; nt < 8; nt++)
                #pragma unroll
                for (int q = 0; q < 4; q++) cacc[mt][nt][q] = 0.f;

        #pragma unroll
        for (int p = 0; p < 3; p++) {
            const __nv_bfloat16* As = (p == 1) ? AloS : AhiS;
            const __nv_bfloat16* Bs = (p == 2) ? BlS : BhS;
            #pragma unroll
            for (int ks = 0; ks < 8; ks++) {
                int k0 = ks * 16;
                uint32_t af[2][4];
                #pragma unroll
                for (int mt = 0; mt < 2; mt++) {
                    const __nv_bfloat16* base = As + (wr + mt * 16) * PITCH + k0;
                    af[mt][0] = *(const uint32_t*)(base + g * PITCH + 2 * tig);
                    af[mt][1] = *(const uint32_t*)(base + (g + 8) * PITCH + 2 * tig);
                    af[mt][2] = *(const uint32_t*)(base + g * PITCH + 8 + 2 * tig);
                    af[mt][3] = *(const uint32_t*)(base + (g + 8) * PITCH + 8 + 2 * tig);
                }
                #pragma unroll
                for (int nt = 0; nt < 8; nt++) {
                    uint32_t bf[2];
                    const __nv_bfloat16* nb = Bs + (wc + nt * 8 + g) * PITCH + k0;
                    bf[0] = *(const uint32_t*)(nb + 2 * tig);
                    bf[1] = *(const uint32_t*)(nb + 8 + 2 * tig);
                    mma16816(cacc[0][nt], af[0], bf);
                    mma16816(cacc[1][nt], af[1], bf);
                }
            }
        }

        // epilogue
        #pragma unroll
        for (int mt = 0; mt < 2; mt++) {
            int row = r0 + wr + mt * 16 + g;
            #pragma unroll
            for (int nt = 0; nt < 8; nt++) {
                int col = wc + nt * 8 + 2 * tig;
                float b0 = biasS[col], b1 = biasS[col + 1];
                float v00 = cacc[mt][nt][0] + b0, v01 = cacc[mt][nt][1] + b1;
                float v10 = cacc[mt][nt][2] + b0, v11 = cacc[mt][nt][3] + b1;
                if (curOsel == 1) {
                    if (row < NN)
                        *(float2*)(d_res0 + (size_t)row * HID + col) = make_float2(v00, v01);
                    if (row + 8 < NN)
                        *(float2*)(d_res0 + (size_t)(row + 8) * HID + col) = make_float2(v10, v11);
                } else {
                    if (row < NN)
                        *(__half2*)(d_hwh + (size_t)row * HID + col) =
                            __floats2half2_rn(v00, v01);
                    if (row + 8 < NN)
                        *(__half2*)(d_hwh + (size_t)(row + 8) * HID + col) =
                            __floats2half2_rn(v10, v11);
                }
            }
        }
    }
}

// ---------------- fused aggregate + bias + LN + residual + relu + mean-acc ----------------
__device__ __forceinline__ void acc_edge(float4& acc, float w, uint2 raw) {
    float2 f0 = __half22float2(*(__half2*)&raw.x);
    float2 f1 = __half22float2(*(__half2*)&raw.y);
    acc.x = fmaf(w, f0.x, acc.x);
    acc.y = fmaf(w, f0.y, acc.y);
    acc.z = fmaf(w, f1.x, acc.z);
    acc.w = fmaf(w, f1.y, acc.w);
}

__global__ __launch_bounds__(256) void agg_ln_k(
    const float* __restrict__ cb, const float* __restrict__ gam,
    const float* __restrict__ bet, int rsel, int osel, int first)
{
    int n = (blockIdx.x * 256 + threadIdx.x) >> 5;
    if (n >= NN) return;
    int lane = threadIdx.x & 31;
    const float* resid = (rsel == 0) ? d_res0 : (rsel == 1) ? d_curA : d_curB;
    float* outp = (osel == 1) ? d_curA : d_curB;
    const uint2* hw2 = (const uint2*)d_hwh;
    size_t loff = (size_t)lane;

    float dn = d_dis[n];
    float sn = dn * dn;
    float4 acc = ((const float4*)cb)[lane];
    acc_edge(acc, sn, hw2[(size_t)n * 32 + loff]);

    int jb = d_rowptr[n], je = d_rowptr[n + 1];
    int j = jb;
    for (; j + 4 <= je; j += 4) {
        float2 a0 = d_adj[j];
        float2 a1 = d_adj[j + 1];
        float2 a2 = d_adj[j + 2];
        float2 a3 = d_adj[j + 3];
        uint2 r0 = hw2[(size_t)__float_as_int(a0.x) * 32 + loff];
        uint2 r1 = hw2[(size_t)__float_as_int(a1.x) * 32 + loff];
        uint2 r2 = hw2[(size_t)__float_as_int(a2.x) * 32 + loff];
        uint2 r3 = hw2[(size_t)__float_as_int(a3.x) * 32 + loff];
        acc_edge(acc, a0.y, r0);
        acc_edge(acc, a1.y, r1);
        acc_edge(acc, a2.y, r2);
        acc_edge(acc, a3.y, r3);
    }
    for (; j < je; j++) {
        float2 a = d_adj[j];
        acc_edge(acc, a.y, hw2[(size_t)__float_as_int(a.x) * 32 + loff]);
    }

    float ss = acc.x + acc.y + acc.z + acc.w;
    #pragma unroll
    for (int o = 16; o > 0; o >>= 1) ss += __shfl_xor_sync(0xffffffffu, ss, o);
    float mu = ss * (1.f / 128.f);
    float dx0 = acc.x - mu, dx1 = acc.y - mu, dx2 = acc.z - mu, dx3 = acc.w - mu;
    float q = dx0 * dx0 + dx1 * dx1 + dx2 * dx2 + dx3 * dx3;
    #pragma unroll
    for (int o = 16; o > 0; o >>= 1) q += __shfl_xor_sync(0xffffffffu, q, o);
    float rstd = rsqrtf(q * (1.f / 128.f) + 1e-5f);

    float4 gv = ((const float4*)gam)[lane];
    float4 bv = ((const float4*)bet)[lane];
    float4 rv = ((const float4*)resid)[(size_t)n * 32 + lane];
    float4 h;
    h.x = fmaxf(fmaf(gv.x, dx0 * rstd, bv.x) + rv.x, 0.f);
    h.y = fmaxf(fmaf(gv.y, dx1 * rstd, bv.y) + rv.y, 0.f);
    h.z = fmaxf(fmaf(gv.z, dx2 * rstd, bv.z) + rv.z, 0.f);
    h.w = fmaxf(fmaf(gv.w, dx3 * rstd, bv.w) + rv.w, 0.f);

    ((float4*)outp)[(size_t)n * 32 + lane] = h;
    float4* xm4 = (float4*)d_xm;
    if (first) {
        xm4[(size_t)n * 32 + lane] = h;
    } else {
        float4 t = xm4[(size_t)n * 32 + lane];
        t.x += h.x; t.y += h.y; t.z += h.z; t.w += h.w;
        xm4[(size_t)n * 32 + lane] = t;
    }
}

// ---------------- graph segment boundaries ----------------
__global__ void mark_k(const int* __restrict__ batch) {
    int n = blockIdx.x * blockDim.x + threadIdx.x;
    if (n >= NN) return;
    int b = batch[n];
    if (n == 0 || batch[n - 1] != b) atomicMin(&d_gstart[b], n);
}

__global__ __launch_bounds__(512) void fix_k() {
    __shared__ int s[520];
    int t = threadIdx.x;
    s[t] = d_gstart[t];
    if (t == 0) s[GG] = NN;
    __syncthreads();
    for (int o = 1; o <= GG; o <<= 1) {
        int v = s[t];
        int u = (t + o <= GG) ? s[t + o] : NN;
        __syncthreads();
        s[t] = min(v, u);
        __syncthreads();
    }
    d_gstart[t] = s[t];
}

// ---------------- pooling ----------------
__global__ __launch_bounds__(128) void pool_k() {
    int g = blockIdx.x, c = threadIdx.x;
    int s = d_gstart[g], e = d_gstart[g + 1];
    float sum = 0.f, mx = 0.f;
    for (int n = s; n < e; n++) {
        float v = d_xm[(size_t)n * HID + c] * 0.25f;
        sum += v;
        mx = fmaxf(mx, v);
    }
    int cnt = e - s;
    d_gmean[g * HID + c] = sum / (float)max(cnt, 1);
    d_gmaxv[g * HID + c] = mx;
}

// ---------------- head ----------------
__global__ __launch_bounds__(128) void head_k(
    const float* __restrict__ hW1, const float* __restrict__ hb1,
    const float* __restrict__ hW2, const float* __restrict__ hb2,
    float* __restrict__ out)
{
    __shared__ float gf[256];
    __shared__ float h1s[128];
    int g = blockIdx.x, t = threadIdx.x;
    gf[t] = d_gmean[g * HID + t];
    gf[128 + t] = d_gmaxv[g * HID + t];
    __syncthreads();
    float acc = hb1[t];
    #pragma unroll 8
    for (int k = 0; k < 256; k++) acc = fmaf(gf[k], hW1[k * HID + t], acc);
    h1s[t] = fmaxf(acc, 0.f);
    __syncthreads();
    if (t < NCLS) {
        float o = hb2[t];
        #pragma unroll 8
        for (int k = 0; k < 128; k++) o = fmaf(h1s[k], hW2[k * NCLS + t], o);
        out[g * NCLS + t] = o;
    }
}

// ---------------- launcher ----------------
extern "C" void kernel_launch(void* const* d_in, const int* in_sizes, int n_in,
                              void* d_out, int out_size) {
    const float* x     = (const float*)d_in[0];
    const int*   ei    = (const int*)d_in[1];
    const int*   batch = (const int*)d_in[2];
    const float* ea    = (const float*)d_in[3];
    const float* eeW1  = (const float*)d_in[4];
    const float* eeb1  = (const float*)d_in[5];
    const float* eeW2  = (const float*)d_in[6];
    const float* eeb2  = (const float*)d_in[7];
    const float* W[4]  = {(const float*)d_in[8],  (const float*)d_in[10],
                          (const float*)d_in[12], (const float*)d_in[14]};
    const float* cbp[4]= {(const float*)d_in[9],  (const float*)d_in[11],
                          (const float*)d_in[13], (const float*)d_in[15]};
    const float* gm[4] = {(const float*)d_in[16], (const float*)d_in[18],
                          (const float*)d_in[20], (const float*)d_in[22]};
    const float* be[4] = {(const float*)d_in[17], (const float*)d_in[19],
                          (const float*)d_in[21], (const float*)d_in[23]};
    const float* resW  = (const float*)d_in[24];
    const float* resB  = (const float*)d_in[25];
    const float* hW1   = (const float*)d_in[26];
    const float* hb1   = (const float*)d_in[27];
    const float* hW2   = (const float*)d_in[28];
    const float* hb2   = (const float*)d_in[29];
    float* out = (float*)d_out;

    cudaFuncSetAttribute(mma_gemm_k, cudaFuncAttributeMaxDynamicSharedMemorySize, SMEM_GEMM);

    const int nblkN = (NN + 255) / 256;
    const int nblkE = (EE + 255) / 256;
    const int tileG = (NN + 127) / 128;
    const int aggG  = (NN + 7) / 8;
    const int edgeG = EE / (128 * ETILES);   // 3125, exact

    init_k<<<nblkN, 256>>>();
    prep_e_k<<<1, 128>>>(eeW1);
    prep_k<<<5, 128>>>(resW, W[0], W[1], W[2], W[3]);
    edge_mma_k<<<edgeG, 256>>>(ea, eeb1, eeW2, eeb2, ei + EE);
    dis_k<<<nblkN, 256>>>();
    scan1_k<<<SCAN_BLOCKS, 1024>>>();
    scan2_k<<<1, 128>>>();
    scan3_k<<<SCAN_BLOCKS, 1024>>>();
    fill_k<<<nblkE, 256>>>(ei, ei + EE);

    // layer 0 GEMM + residual projection fused (shared A = x):
    //   pass1: x @ W0 -> d_hwh ; pass2: x @ resW + resB -> d_res0
    mma_gemm_k<<<tileG, 256, SMEM_GEMM>>>(x, 0, 0, 1, IN_C, nullptr, 1, 0, resB);
    agg_ln_k<<<aggG, 256>>>(cbp[0], gm[0], be[0], 0, 1, 1);
    // layer 1
    mma_gemm_k<<<tileG, 256, SMEM_GEMM>>>(nullptr, 1, 0, 2, HID, nullptr, 0, -1, nullptr);
    agg_ln_k<<<aggG, 256>>>(cbp[1], gm[1], be[1], 1, 2, 0);
    // layer 2
    mma_gemm_k<<<tileG, 256, SMEM_GEMM>>>(nullptr, 2, 0, 3, HID, nullptr, 0, -1, nullptr);
    agg_ln_k<<<aggG, 256>>>(cbp[2], gm[2], be[2], 2, 1, 0);
    // layer 3
    mma_gemm_k<<<tileG, 256, SMEM_GEMM>>>(nullptr, 1, 0, 4, HID, nullptr, 0, -1, nullptr);
    agg_ln_k<<<aggG, 256>>>(cbp[3], gm[3], be[3], 1, 2, 0);

    mark_k<<<nblkN, 256>>>(batch);
    fix_k<<<1, 512>>>();
    pool_k<<<GG, 128>>>();
    head_k<<<GG, 128>>>(hW1, hb1, hW2, hb2, out);
}